// round 10
// baseline (speedup 1.0000x reference)
#include <cuda_runtime.h>
#include <math.h>

#define NPIX 4140      // 46*90
#define CIN  256
#define HEADS 8
#define DHEAD 32
#define NTK  65        // key tiles of 64 (65*64 = 4160)
#define KSTR 72
#define VSTR 68
#define LOG2E 1.4426950408889634f

typedef unsigned int uint;

// ---------------- scratch (no allocations allowed) ----------------
__device__ float  g_Q[CIN * NPIX];
__device__ float  g_K[CIN * NPIX];
__device__ float  g_V[CIN * NPIX];
__device__ float2 g_Os[CIN * NPIX];     // attention out, pre-split (hi, lo)
__device__ float2 g_Xq[CIN * NPIX];     // query, pre-split (hi, lo)
__device__ float  g_Lq[NTK * 64];       // log-quad bias * log2(e), padded

// ---------------- helpers ----------------
__device__ __forceinline__ uint to_tf32(float f) {
    uint u;
    asm("cvt.rna.tf32.f32 %0, %1;" : "=r"(u) : "f"(f));
    return u;
}

__device__ __forceinline__ float ex2(float x) {
    float y;
    asm("ex2.approx.f32 %0, %1;" : "=f"(y) : "f"(x));
    return y;
}

__device__ __forceinline__ float2 split2(float x) {
    float h = __uint_as_float(to_tf32(x));
    float l = __uint_as_float(to_tf32(x - h));
    return make_float2(h, l);
}

__device__ __forceinline__ void mma_tf32(float c[4],
                                         uint a0, uint a1, uint a2, uint a3,
                                         uint b0, uint b1) {
    asm volatile(
        "mma.sync.aligned.m16n8k8.row.col.f32.tf32.tf32.f32 "
        "{%0,%1,%2,%3}, {%4,%5,%6,%7}, {%8,%9}, {%0,%1,%2,%3};"
        : "+f"(c[0]), "+f"(c[1]), "+f"(c[2]), "+f"(c[3])
        : "r"(a0), "r"(a1), "r"(a2), "r"(a3), "r"(b0), "r"(b1));
}

__device__ __forceinline__ void cp_async16(void* dst, const void* src, int src_sz) {
    uint d = (uint)__cvta_generic_to_shared(dst);
    asm volatile("cp.async.cg.shared.global [%0], [%1], 16, %2;"
                 :: "r"(d), "l"(src), "r"(src_sz));
}
__device__ __forceinline__ void cp_commit() { asm volatile("cp.async.commit_group;"); }
__device__ __forceinline__ void cp_wait0()  { asm volatile("cp.async.wait_group 0;"); }

// ============================================================================
// Pre-split query -> g_Xq (interleaved hi/lo). Weights stay raw (A-side splits
// are cheap in-register; only the x8-reused B-side needed pre-splitting).
// ============================================================================
#define NX_TOT (CIN * NPIX)            // 1059840

__global__ __launch_bounds__(256)
void split_x(const float* __restrict__ query)
{
    int i = blockIdx.x * 256 + threadIdx.x;
    if (i < NX_TOT) g_Xq[i] = split2(query[i]);
}

// ============================================================================
// 3xTF32 GEMM: raw-f32 W in smem (A split in regs), pre-split X (float2).
// Tile 64k x 128n, 256 thr / 8 warps (4 along k x 2 along n). k-step 32.
// cp.async double-buffered, one sync per k-step. 84 KB smem -> 2 CTAs/SM.
// ============================================================================
#define GWSTR 36
#define GX2STR 132                      // float2 stride
#define SW_ELE (64 * GWSTR)             // floats per stage
#define SX_ELE (32 * GX2STR)            // float2 per stage
#define GSMEM_BYTES ((2 * SW_ELE) * 4 + (2 * SX_ELE) * 8)

__device__ __forceinline__
void gemm_core(const float2* __restrict__ Xs,
               const float* __restrict__ W,
               const float* __restrict__ bias, float* __restrict__ Y)
{
    extern __shared__ float dsm[];
    float*  sW  = dsm;                              // [2][64][GWSTR] raw
    float2* sXs = (float2*)(dsm + 2 * SW_ELE);      // [2][32][GX2STR]

    const int tid  = threadIdx.x;
    const int w    = tid >> 5;
    const int kw   = w & 3;
    const int nh   = w >> 2;
    const int lane = tid & 31;
    const int g    = lane >> 2;
    const int tig  = lane & 3;
    const int k0   = blockIdx.y * 64;
    const int n0   = blockIdx.x * 128;

    // ---- prologue: stage 0 ----
    {
        #pragma unroll
        for (int r = 0; r < 2; r++) {               // W: 64x32 raw
            int idx = tid + 256 * r;
            int wk = idx >> 3, wc = (idx & 7) * 4;
            cp_async16(&sW[wk * GWSTR + wc], &W[(k0 + wk) * CIN + wc], 16);
        }
        #pragma unroll
        for (int r = 0; r < 8; r++) {               // X: 32c x 128n float2
            int idx = tid + 256 * r;
            int xc = idx >> 6, xn2 = (idx & 63) * 2;
            int n = n0 + xn2;
            int ok = (n < NPIX);
            cp_async16(&sXs[xc * GX2STR + xn2], &Xs[xc * NPIX + (ok ? n : 0)],
                       ok ? 16 : 0);
        }
        cp_commit();
    }

    float acc[8][4];
    #pragma unroll
    for (int nb = 0; nb < 8; nb++)
        #pragma unroll
        for (int i = 0; i < 4; i++) acc[nb][i] = 0.f;

    cp_wait0();
    __syncthreads();

    #pragma unroll
    for (int it = 0; it < 8; it++) {
        const int cur = it & 1;
        const int nxt = cur ^ 1;
        const bool more = (it + 1 < 8);
        float*  sWc = sW  + cur * SW_ELE;
        float2* sXc = sXs + cur * SX_ELE;

        // ---- issue next stage copies ----
        if (more) {
            const int cc = (it + 1) * 32;
            float*  sWn = sW  + nxt * SW_ELE;
            float2* sXn = sXs + nxt * SX_ELE;
            #pragma unroll
            for (int r = 0; r < 2; r++) {
                int idx = tid + 256 * r;
                int wk = idx >> 3, wc = (idx & 7) * 4;
                cp_async16(&sWn[wk * GWSTR + wc], &W[(k0 + wk) * CIN + cc + wc], 16);
            }
            #pragma unroll
            for (int r = 0; r < 8; r++) {
                int idx = tid + 256 * r;
                int xc = idx >> 6, xn2 = (idx & 63) * 2;
                int n = n0 + xn2;
                int ok = (n < NPIX);
                cp_async16(&sXn[xc * GX2STR + xn2],
                           &Xs[(cc + xc) * NPIX + (ok ? n : 0)], ok ? 16 : 0);
            }
            cp_commit();
        }

        // ---- compute on current stage ----
        #pragma unroll
        for (int kb = 0; kb < 4; kb++) {
            const int ar = (kw * 16 + g) * GWSTR + kb * 8 + tig;
            // raw A values, split hi/lo in registers (8 values, cheap)
            float2 a0 = split2(sWc[ar]);
            float2 a1 = split2(sWc[ar + 8 * GWSTR]);
            float2 a2 = split2(sWc[ar + 4]);
            float2 a3 = split2(sWc[ar + 8 * GWSTR + 4]);
            uint ah0 = __float_as_uint(a0.x), al0 = __float_as_uint(a0.y);
            uint ah1 = __float_as_uint(a1.x), al1 = __float_as_uint(a1.y);
            uint ah2 = __float_as_uint(a2.x), al2 = __float_as_uint(a2.y);
            uint ah3 = __float_as_uint(a3.x), al3 = __float_as_uint(a3.y);
            const int brow0 = (kb * 8 + tig) * GX2STR + nh * 64 + g;
            const int brow1 = brow0 + 4 * GX2STR;
            #pragma unroll
            for (int nb = 0; nb < 8; nb++) {
                float2 b0 = sXc[brow0 + nb * 8];
                float2 b1 = sXc[brow1 + nb * 8];
                uint bh0 = __float_as_uint(b0.x), bl0 = __float_as_uint(b0.y);
                uint bh1 = __float_as_uint(b1.x), bl1 = __float_as_uint(b1.y);
                mma_tf32(acc[nb], ah0, ah1, ah2, ah3, bh0, bh1);
                mma_tf32(acc[nb], ah0, ah1, ah2, ah3, bl0, bl1);
                mma_tf32(acc[nb], al0, al1, al2, al3, bh0, bh1);
            }
        }

        if (more) cp_wait0();
        __syncthreads();
    }

    const int r0 = k0 + kw * 16 + g;
    const int r1 = r0 + 8;
    const float bv0 = __ldg(&bias[r0]);
    const float bv1 = __ldg(&bias[r1]);
    #pragma unroll
    for (int nb = 0; nb < 8; nb++) {
        int n = n0 + nh * 64 + nb * 8 + 2 * tig;
        if (n < NPIX) {
            float2 y0 = make_float2(acc[nb][0] + bv0, acc[nb][1] + bv0);
            float2 y1 = make_float2(acc[nb][2] + bv1, acc[nb][3] + bv1);
            *(float2*)&Y[r0 * NPIX + n] = y0;
            *(float2*)&Y[r1 * NPIX + n] = y1;
        }
    }
}

__global__ __launch_bounds__(256)
void gemm_qkv(const float* __restrict__ qw, const float* __restrict__ qb,
              const float* __restrict__ kw_, const float* __restrict__ kb,
              const float* __restrict__ vw, const float* __restrict__ vb,
              const float* __restrict__ lq)
{
    int z = blockIdx.z;
    if (z == 0 && blockIdx.x == 0 && blockIdx.y == 0) {
        for (int i = threadIdx.x; i < NTK * 64; i += 256)
            g_Lq[i] = (i < NPIX) ? lq[i] * LOG2E : -1e30f;
    }
    const float* W = (z == 0) ? qw : (z == 1) ? kw_ : vw;
    const float* B = (z == 0) ? qb : (z == 1) ? kb : vb;
    float* Y       = (z == 0) ? g_Q : (z == 1) ? g_K : g_V;
    gemm_core(g_Xq, W, B, Y);
}

__global__ __launch_bounds__(256)
void gemm_proj(const float* __restrict__ W, const float* __restrict__ B,
               float* __restrict__ Y)
{
    gemm_core(g_Os, W, B, Y);
}

// ============================================================================
// Flash attention, tf32 mma.sync, fixed-shift base-2 softmax (scores <= ~0
// with ~80 units of margin; shift-invariance makes the fixed shift exact).
//   Block: 512 threads / 16 warps, 256 queries -> grid 17 x 8 = one wave.
//   exp2 (MUFU) interleaved with PV MMAs per key-block to avoid phase bursts.
//   p fed to HMMA raw (HW truncates to tf32, same path as cp.async'd K).
//   V smem key-permuted within 8-groups so P's C-fragment IS the A-fragment.
//   Epilogue writes g_Os pre-split (hi,lo) for the 3xTF32 projection GEMM.
// ============================================================================
__global__ __launch_bounds__(512)
void attn_kernel()
{
    __shared__ float sK[2][DHEAD * KSTR];   // [d][key], natural key order
    __shared__ float sV[2][DHEAD * VSTR];   // [d][kslot], permuted key order

    const int tid  = threadIdx.x;
    const int w    = tid >> 5;
    const int lane = tid & 31;
    const int g    = lane >> 2;
    const int tig  = lane & 3;
    const int h    = blockIdx.y;
    const int qb   = blockIdx.x;

    const int q_row0 = qb * 256 + w * 16 + g;
    const int q_row1 = q_row0 + 8;

    // fill-role indices: 512 threads cover 32d x 64key in one shot
    const int fd = tid >> 4;            // 0..31
    const int fc = tid & 15;            // 0..15 -> key chunk *4

    // ---- Q fragments (scale includes log2 e) ----
    const float scale = 0.17677669529663687f * LOG2E;
    const int r0 = (q_row0 < NPIX) ? q_row0 : (NPIX - 1);
    const int r1 = (q_row1 < NPIX) ? q_row1 : (NPIX - 1);
    uint qa[4][4];
    #pragma unroll
    for (int kbq = 0; kbq < 4; kbq++) {
        int d0 = kbq * 8;
        qa[kbq][0] = to_tf32(g_Q[(h * DHEAD + d0 + tig)     * NPIX + r0] * scale);
        qa[kbq][1] = to_tf32(g_Q[(h * DHEAD + d0 + tig)     * NPIX + r1] * scale);
        qa[kbq][2] = to_tf32(g_Q[(h * DHEAD + d0 + tig + 4) * NPIX + r0] * scale);
        qa[kbq][3] = to_tf32(g_Q[(h * DHEAD + d0 + tig + 4) * NPIX + r1] * scale);
    }

    float o[4][4];
    #pragma unroll
    for (int db = 0; db < 4; db++)
        #pragma unroll
        for (int j = 0; j < 4; j++) o[db][j] = 0.f;

    float l0 = 0.f, l1 = 0.f;
    float4 rv4;

    // ---------- prologue: tile 0 ----------
    {
        int key = fc * 4;   // t = 0, always < NPIX
        cp_async16(&sK[0][fd * KSTR + key], &g_K[(h * DHEAD + fd) * NPIX + key], 16);
        rv4 = *(const float4*)&g_V[(h * DHEAD + fd) * NPIX + key];
        cp_commit();
        float4 v = rv4;
        v.x = __uint_as_float(to_tf32(v.x));
        v.y = __uint_as_float(to_tf32(v.y));
        v.z = __uint_as_float(to_tf32(v.z));
        v.w = __uint_as_float(to_tf32(v.w));
        int base = fd * VSTR + 8 * (fc >> 1) + 2 * (fc & 1);
        *(float2*)&sV[0][base]     = make_float2(v.x, v.z);
        *(float2*)&sV[0][base + 4] = make_float2(v.y, v.w);
    }
    cp_wait0();
    __syncthreads();

    for (int t = 0; t < NTK; t++) {
        const int cur = t & 1;
        const int nxt = cur ^ 1;
        const bool more = (t + 1 < NTK);

        // ---- issue next K (cp.async) and next V (LDG into regs) ----
        if (more) {
            int key = (t + 1) * 64 + fc * 4;
            int keyc = (key < NPIX) ? key : 0;
            int sz = (key < NPIX) ? 16 : 0;
            cp_async16(&sK[nxt][fd * KSTR + fc * 4],
                       &g_K[(h * DHEAD + fd) * NPIX + keyc], sz);
            rv4 = (key < NPIX)
                  ? *(const float4*)&g_V[(h * DHEAD + fd) * NPIX + key]
                  : make_float4(0.f, 0.f, 0.f, 0.f);
            cp_commit();
        }

        // ---- S = Q K^T ----
        float c[8][4];
        #pragma unroll
        for (int nb = 0; nb < 8; nb++) {
            c[nb][0] = c[nb][1] = c[nb][2] = c[nb][3] = 0.f;
            #pragma unroll
            for (int kb = 0; kb < 4; kb++) {
                uint b0 = __float_as_uint(sK[cur][(kb * 8 + tig)     * KSTR + nb * 8 + g]);
                uint b1 = __float_as_uint(sK[cur][(kb * 8 + tig + 4) * KSTR + nb * 8 + g]);
                mma_tf32(c[nb], qa[kb][0], qa[kb][1], qa[kb][2], qa[kb][3], b0, b1);
            }
        }

        // ---- fused bias + exp2 + PV per key-block (MUFU/tensor interleave) ----
        float ps0 = 0.f, ps1 = 0.f;
        #pragma unroll
        for (int nb = 0; nb < 8; nb++) {
            float2 lb = *(const float2*)&g_Lq[t * 64 + nb * 8 + 2 * tig];
            float p0 = ex2(c[nb][0] + lb.x);
            float p1 = ex2(c[nb][1] + lb.y);
            float p2 = ex2(c[nb][2] + lb.x);
            float p3 = ex2(c[nb][3] + lb.y);
            ps0 += p0 + p1;
            ps1 += p2 + p3;
            // C-fragment used directly as A-fragment (keys permuted in sV);
            // p left raw f32 -> HW truncates to tf32 inside HMMA.
            uint pa0 = __float_as_uint(p0);
            uint pa1 = __float_as_uint(p2);
            uint pa2 = __float_as_uint(p1);
            uint pa3 = __float_as_uint(p3);
            #pragma unroll
            for (int db = 0; db < 4; db++) {
                uint b0 = __float_as_uint(sV[cur][(db * 8 + g) * VSTR + nb * 8 + tig]);
                uint b1 = __float_as_uint(sV[cur][(db * 8 + g) * VSTR + nb * 8 + tig + 4]);
                mma_tf32(o[db], pa0, pa1, pa2, pa3, b0, b1);
            }
        }
        l0 += ps0;
        l1 += ps1;

        // ---- store next V (permuted) into the other buffer ----
        if (more) {
            float4 v = rv4;
            v.x = __uint_as_float(to_tf32(v.x));
            v.y = __uint_as_float(to_tf32(v.y));
            v.z = __uint_as_float(to_tf32(v.z));
            v.w = __uint_as_float(to_tf32(v.w));
            int base = fd * VSTR + 8 * (fc >> 1) + 2 * (fc & 1);
            *(float2*)&sV[nxt][base]     = make_float2(v.x, v.z);
            *(float2*)&sV[nxt][base + 4] = make_float2(v.y, v.w);
        }

        if (more) cp_wait0();
        __syncthreads();
    }

    // ---- final lane-quad reduction of l, then pre-split epilogue ----
    l0 += __shfl_xor_sync(0xffffffffu, l0, 1);
    l0 += __shfl_xor_sync(0xffffffffu, l0, 2);
    l1 += __shfl_xor_sync(0xffffffffu, l1, 1);
    l1 += __shfl_xor_sync(0xffffffffu, l1, 2);
    float inv0 = 1.f / l0;
    float inv1 = 1.f / l1;
    #pragma unroll
    for (int db = 0; db < 4; db++) {
        int d = db * 8 + 2 * tig;
        if (q_row0 < NPIX) {
            g_Os[(h * DHEAD + d)     * NPIX + q_row0] = split2(o[db][0] * inv0);
            g_Os[(h * DHEAD + d + 1) * NPIX + q_row0] = split2(o[db][1] * inv0);
        }
        if (q_row1 < NPIX) {
            g_Os[(h * DHEAD + d)     * NPIX + q_row1] = split2(o[db][2] * inv1);
            g_Os[(h * DHEAD + d + 1) * NPIX + q_row1] = split2(o[db][3] * inv1);
        }
    }
}

// ============================================================================
extern "C" void kernel_launch(void* const* d_in, const int* in_sizes, int n_in,
                              void* d_out, int out_size)
{
    const float* query = (const float*)d_in[0];
    const float* q_w   = (const float*)d_in[1];
    const float* q_b   = (const float*)d_in[2];
    const float* k_w   = (const float*)d_in[3];
    const float* k_b   = (const float*)d_in[4];
    const float* v_w   = (const float*)d_in[5];
    const float* v_b   = (const float*)d_in[6];
    const float* p_w   = (const float*)d_in[7];
    const float* p_b   = (const float*)d_in[8];
    const float* lqw   = (const float*)d_in[9];
    float* out = (float*)d_out;

    cudaFuncSetAttribute(gemm_qkv,  cudaFuncAttributeMaxDynamicSharedMemorySize, GSMEM_BYTES);
    cudaFuncSetAttribute(gemm_proj, cudaFuncAttributeMaxDynamicSharedMemorySize, GSMEM_BYTES);

    split_x<<<(NX_TOT + 255) / 256, 256>>>(query);

    dim3 gq((NPIX + 127) / 128, 4, 3);                     // 33 x 4 x 3
    gemm_qkv<<<gq, 256, GSMEM_BYTES>>>(q_w, q_b, k_w, k_b, v_w, v_b, lqw);

    dim3 ga((NPIX + 255) / 256, HEADS, 1);                 // 17 x 8 = 136
    attn_kernel<<<ga, 512>>>();                            // -> g_Os (pre-split)

    dim3 gp((NPIX + 127) / 128, 4, 1);                     // 33 x 4
    gemm_proj<<<gp, 256, GSMEM_BYTES>>>(p_w, p_b, out);
}

// round 11
// speedup vs baseline: 1.1712x; 1.1712x over previous
#include <cuda_runtime.h>
#include <cuda_fp16.h>
#include <math.h>

#define NPIX 4140      // 46*90
#define CIN  256
#define HEADS 8
#define DHEAD 32
#define NTK  65        // key tiles of 64 (65*64 = 4160)
#define LOG2E 1.4426950408889634f

typedef unsigned int uint;

// ---------------- scratch (no allocations allowed) ----------------
__device__ float  g_Q[CIN * NPIX];
__device__ float  g_K[CIN * NPIX];
__device__ float  g_V[CIN * NPIX];
__device__ float2 g_Os[CIN * NPIX];     // attention out, pre-split (hi, lo)
__device__ float2 g_Xq[CIN * NPIX];     // query, pre-split (hi, lo)
__device__ float  g_Lq[NTK * 64];       // log-quad bias * log2(e), padded

// ---------------- helpers ----------------
__device__ __forceinline__ uint to_tf32(float f) {
    uint u;
    asm("cvt.rna.tf32.f32 %0, %1;" : "=r"(u) : "f"(f));
    return u;
}

__device__ __forceinline__ float ex2(float x) {
    float y;
    asm("ex2.approx.f32 %0, %1;" : "=f"(y) : "f"(x));
    return y;
}

__device__ __forceinline__ float2 split2(float x) {
    float h = __uint_as_float(to_tf32(x));
    float l = __uint_as_float(to_tf32(x - h));
    return make_float2(h, l);
}

__device__ __forceinline__ uint packh2(float a, float b) {
    // half2: low = a, high = b
    uint r;
    asm("cvt.rn.f16x2.f32 %0, %2, %1;" : "=r"(r) : "f"(a), "f"(b));
    return r;
}

__device__ __forceinline__ void mma_tf32(float c[4],
                                         uint a0, uint a1, uint a2, uint a3,
                                         uint b0, uint b1) {
    asm volatile(
        "mma.sync.aligned.m16n8k8.row.col.f32.tf32.tf32.f32 "
        "{%0,%1,%2,%3}, {%4,%5,%6,%7}, {%8,%9}, {%0,%1,%2,%3};"
        : "+f"(c[0]), "+f"(c[1]), "+f"(c[2]), "+f"(c[3])
        : "r"(a0), "r"(a1), "r"(a2), "r"(a3), "r"(b0), "r"(b1));
}

__device__ __forceinline__ void mma_f16(float c[4],
                                        uint a0, uint a1, uint a2, uint a3,
                                        uint b0, uint b1) {
    asm volatile(
        "mma.sync.aligned.m16n8k16.row.col.f32.f16.f16.f32 "
        "{%0,%1,%2,%3}, {%4,%5,%6,%7}, {%8,%9}, {%0,%1,%2,%3};"
        : "+f"(c[0]), "+f"(c[1]), "+f"(c[2]), "+f"(c[3])
        : "r"(a0), "r"(a1), "r"(a2), "r"(a3), "r"(b0), "r"(b1));
}

__device__ __forceinline__ void cp_async16(void* dst, const void* src, int src_sz) {
    uint d = (uint)__cvta_generic_to_shared(dst);
    asm volatile("cp.async.cg.shared.global [%0], [%1], 16, %2;"
                 :: "r"(d), "l"(src), "r"(src_sz));
}
__device__ __forceinline__ void cp_commit() { asm volatile("cp.async.commit_group;"); }
__device__ __forceinline__ void cp_wait0()  { asm volatile("cp.async.wait_group 0;"); }

// ============================================================================
// Pre-split query -> g_Xq (interleaved hi/lo).
// ============================================================================
#define NX_TOT (CIN * NPIX)            // 1059840

__global__ __launch_bounds__(256)
void split_x(const float* __restrict__ query)
{
    int i = blockIdx.x * 256 + threadIdx.x;
    if (i < NX_TOT) g_Xq[i] = split2(query[i]);
}

// ============================================================================
// 3xTF32 GEMM: raw-f32 W in smem (A split in regs), pre-split X (float2).
// Tile 64k x 128n, 256 thr / 8 warps. k-step 32, cp.async double-buffered.
// ============================================================================
#define GWSTR 36
#define GX2STR 132
#define SW_ELE (64 * GWSTR)
#define SX_ELE (32 * GX2STR)
#define GSMEM_BYTES ((2 * SW_ELE) * 4 + (2 * SX_ELE) * 8)

__device__ __forceinline__
void gemm_core(const float2* __restrict__ Xs,
               const float* __restrict__ W,
               const float* __restrict__ bias, float* __restrict__ Y)
{
    extern __shared__ float dsm[];
    float*  sW  = dsm;
    float2* sXs = (float2*)(dsm + 2 * SW_ELE);

    const int tid  = threadIdx.x;
    const int w    = tid >> 5;
    const int kw   = w & 3;
    const int nh   = w >> 2;
    const int lane = tid & 31;
    const int g    = lane >> 2;
    const int tig  = lane & 3;
    const int k0   = blockIdx.y * 64;
    const int n0   = blockIdx.x * 128;

    {
        #pragma unroll
        for (int r = 0; r < 2; r++) {
            int idx = tid + 256 * r;
            int wk = idx >> 3, wc = (idx & 7) * 4;
            cp_async16(&sW[wk * GWSTR + wc], &W[(k0 + wk) * CIN + wc], 16);
        }
        #pragma unroll
        for (int r = 0; r < 8; r++) {
            int idx = tid + 256 * r;
            int xc = idx >> 6, xn2 = (idx & 63) * 2;
            int n = n0 + xn2;
            int ok = (n < NPIX);
            cp_async16(&sXs[xc * GX2STR + xn2], &Xs[xc * NPIX + (ok ? n : 0)],
                       ok ? 16 : 0);
        }
        cp_commit();
    }

    float acc[8][4];
    #pragma unroll
    for (int nb = 0; nb < 8; nb++)
        #pragma unroll
        for (int i = 0; i < 4; i++) acc[nb][i] = 0.f;

    cp_wait0();
    __syncthreads();

    #pragma unroll
    for (int it = 0; it < 8; it++) {
        const int cur = it & 1;
        const int nxt = cur ^ 1;
        const bool more = (it + 1 < 8);
        float*  sWc = sW  + cur * SW_ELE;
        float2* sXc = sXs + cur * SX_ELE;

        if (more) {
            const int cc = (it + 1) * 32;
            float*  sWn = sW  + nxt * SW_ELE;
            float2* sXn = sXs + nxt * SX_ELE;
            #pragma unroll
            for (int r = 0; r < 2; r++) {
                int idx = tid + 256 * r;
                int wk = idx >> 3, wc = (idx & 7) * 4;
                cp_async16(&sWn[wk * GWSTR + wc], &W[(k0 + wk) * CIN + cc + wc], 16);
            }
            #pragma unroll
            for (int r = 0; r < 8; r++) {
                int idx = tid + 256 * r;
                int xc = idx >> 6, xn2 = (idx & 63) * 2;
                int n = n0 + xn2;
                int ok = (n < NPIX);
                cp_async16(&sXn[xc * GX2STR + xn2],
                           &Xs[(cc + xc) * NPIX + (ok ? n : 0)], ok ? 16 : 0);
            }
            cp_commit();
        }

        #pragma unroll
        for (int kb = 0; kb < 4; kb++) {
            const int ar = (kw * 16 + g) * GWSTR + kb * 8 + tig;
            float2 a0 = split2(sWc[ar]);
            float2 a1 = split2(sWc[ar + 8 * GWSTR]);
            float2 a2 = split2(sWc[ar + 4]);
            float2 a3 = split2(sWc[ar + 8 * GWSTR + 4]);
            uint ah0 = __float_as_uint(a0.x), al0 = __float_as_uint(a0.y);
            uint ah1 = __float_as_uint(a1.x), al1 = __float_as_uint(a1.y);
            uint ah2 = __float_as_uint(a2.x), al2 = __float_as_uint(a2.y);
            uint ah3 = __float_as_uint(a3.x), al3 = __float_as_uint(a3.y);
            const int brow0 = (kb * 8 + tig) * GX2STR + nh * 64 + g;
            const int brow1 = brow0 + 4 * GX2STR;
            #pragma unroll
            for (int nb = 0; nb < 8; nb++) {
                float2 b0 = sXc[brow0 + nb * 8];
                float2 b1 = sXc[brow1 + nb * 8];
                uint bh0 = __float_as_uint(b0.x), bl0 = __float_as_uint(b0.y);
                uint bh1 = __float_as_uint(b1.x), bl1 = __float_as_uint(b1.y);
                mma_tf32(acc[nb], ah0, ah1, ah2, ah3, bh0, bh1);
                mma_tf32(acc[nb], ah0, ah1, ah2, ah3, bl0, bl1);
                mma_tf32(acc[nb], al0, al1, al2, al3, bh0, bh1);
            }
        }

        if (more) cp_wait0();
        __syncthreads();
    }

    const int r0 = k0 + kw * 16 + g;
    const int r1 = r0 + 8;
    const float bv0 = __ldg(&bias[r0]);
    const float bv1 = __ldg(&bias[r1]);
    #pragma unroll
    for (int nb = 0; nb < 8; nb++) {
        int n = n0 + nh * 64 + nb * 8 + 2 * tig;
        if (n < NPIX) {
            float2 y0 = make_float2(acc[nb][0] + bv0, acc[nb][1] + bv0);
            float2 y1 = make_float2(acc[nb][2] + bv1, acc[nb][3] + bv1);
            *(float2*)&Y[r0 * NPIX + n] = y0;
            *(float2*)&Y[r1 * NPIX + n] = y1;
        }
    }
}

__global__ __launch_bounds__(256)
void gemm_qkv(const float* __restrict__ qw, const float* __restrict__ qb,
              const float* __restrict__ kw_, const float* __restrict__ kb,
              const float* __restrict__ vw, const float* __restrict__ vb,
              const float* __restrict__ lq)
{
    int z = blockIdx.z;
    if (z == 0 && blockIdx.x == 0 && blockIdx.y == 0) {
        for (int i = threadIdx.x; i < NTK * 64; i += 256)
            g_Lq[i] = (i < NPIX) ? lq[i] * LOG2E : -1e30f;
    }
    const float* W = (z == 0) ? qw : (z == 1) ? kw_ : vw;
    const float* B = (z == 0) ? qb : (z == 1) ? kb : vb;
    float* Y       = (z == 0) ? g_Q : (z == 1) ? g_K : g_V;
    gemm_core(g_Xq, W, B, Y);
}

__global__ __launch_bounds__(256)
void gemm_proj(const float* __restrict__ W, const float* __restrict__ B,
               float* __restrict__ Y)
{
    gemm_core(g_Os, W, B, Y);
}

// ============================================================================
// Flash attention, fp16 m16n8k16 mma.sync (fp32 accumulate), fixed-shift
// base-2 softmax (scores <= ~0 with huge margin; shift-invariance => exact).
//   Block: 512 threads / 16 warps, 256 queries -> grid 17 x 8 = one wave.
//   sK2: [16 d-pairs][64 keys] half2 (K[2dp][key],K[2dp+1][key]), 288B rows.
//   sV : [32 d][32 key-pairs] half2 (V[d][2kp],V[d][2kp+1]),     144B rows.
//   Both layouts proven conflict-free for their B-fragment access patterns.
//   P's fp16 A-fragment == S's C-fragment pairs (no shuffles, no permutation).
//   Epilogue writes g_Os pre-split (hi,lo) for the 3xTF32 projection GEMM.
// ============================================================================
#define KS2 72     // uints per dp row (288 B)
#define VS2 36     // uints per d row  (144 B)

__global__ __launch_bounds__(512)
void attn_kernel()
{
    __shared__ uint sK2[2][16 * KS2];
    __shared__ uint sV [2][32 * VS2];

    const int tid  = threadIdx.x;
    const int lane = tid & 31;
    const int w    = tid >> 5;
    const int g    = lane >> 2;
    const int tig  = lane & 3;
    const int h    = blockIdx.y;
    const int qb   = blockIdx.x;

    const int q_row0 = qb * 256 + w * 16 + g;
    const int q_row1 = q_row0 + 8;

    // fill roles
    const int fdp = tid >> 4;           // K: d-pair 0..15 (tid<256); V: d 0..31
    const int fkc = tid & 15;           // key chunk of 4

    // ---- Q fragments, fp16 (scale includes log2 e) ----
    const float scale = 0.17677669529663687f * LOG2E;
    const int r0 = (q_row0 < NPIX) ? q_row0 : (NPIX - 1);
    const int r1 = (q_row1 < NPIX) ? q_row1 : (NPIX - 1);
    uint qa[2][4];
    #pragma unroll
    for (int kc = 0; kc < 2; kc++) {
        int d0 = kc * 16 + 2 * tig;
        const float* Qh = g_Q + (size_t)h * DHEAD * NPIX;
        qa[kc][0] = packh2(Qh[(d0)     * NPIX + r0] * scale, Qh[(d0 + 1) * NPIX + r0] * scale);
        qa[kc][1] = packh2(Qh[(d0)     * NPIX + r1] * scale, Qh[(d0 + 1) * NPIX + r1] * scale);
        qa[kc][2] = packh2(Qh[(d0 + 8) * NPIX + r0] * scale, Qh[(d0 + 9) * NPIX + r0] * scale);
        qa[kc][3] = packh2(Qh[(d0 + 8) * NPIX + r1] * scale, Qh[(d0 + 9) * NPIX + r1] * scale);
    }

    float o[4][4];
    #pragma unroll
    for (int db = 0; db < 4; db++)
        #pragma unroll
        for (int j = 0; j < 4; j++) o[db][j] = 0.f;

    float l0 = 0.f, l1 = 0.f;
    float4 rka, rkb, rva;

    const float* Kbase = g_K + (size_t)h * DHEAD * NPIX;
    const float* Vbase = g_V + (size_t)h * DHEAD * NPIX;

    // ---------- prologue: load + store tile 0 ----------
    {
        int key0 = fkc * 4;             // t = 0, always valid
        if (tid < 256) {
            rka = *(const float4*)&Kbase[(2 * fdp)     * NPIX + key0];
            rkb = *(const float4*)&Kbase[(2 * fdp + 1) * NPIX + key0];
            uint4 kk;
            kk.x = packh2(rka.x, rkb.x);
            kk.y = packh2(rka.y, rkb.y);
            kk.z = packh2(rka.z, rkb.z);
            kk.w = packh2(rka.w, rkb.w);
            *(uint4*)&sK2[0][fdp * KS2 + key0] = kk;
        }
        rva = *(const float4*)&Vbase[fdp * NPIX + key0];   // fdp = d for V role? no:
        // V role uses all 512 threads: d = tid>>4 (0..31)
        uint2 vv;
        vv.x = packh2(rva.x, rva.y);
        vv.y = packh2(rva.z, rva.w);
        *(uint2*)&sV[0][fdp * VS2 + fkc * 2] = vv;
    }
    __syncthreads();

    for (int t = 0; t < NTK; t++) {
        const int cur = t & 1;
        const int nxt = cur ^ 1;
        const bool more = (t + 1 < NTK);

        // ---- issue next-tile global loads into registers ----
        if (more) {
            int key0 = (t + 1) * 64 + fkc * 4;
            bool ok = (key0 < NPIX);        // NPIX % 4 == 0, so full float4
            int keyc = ok ? key0 : 0;
            if (tid < 256) {
                float4 ka = *(const float4*)&Kbase[(2 * fdp)     * NPIX + keyc];
                float4 kb = *(const float4*)&Kbase[(2 * fdp + 1) * NPIX + keyc];
                rka = ok ? ka : make_float4(0.f, 0.f, 0.f, 0.f);
                rkb = ok ? kb : make_float4(0.f, 0.f, 0.f, 0.f);
            }
            float4 va = *(const float4*)&Vbase[fdp * NPIX + keyc];
            rva = ok ? va : make_float4(0.f, 0.f, 0.f, 0.f);
        }

        // ---- S = Q K^T : 8 nb x 2 kc of m16n8k16 ----
        float c[8][4];
        #pragma unroll
        for (int nb = 0; nb < 8; nb++) {
            c[nb][0] = c[nb][1] = c[nb][2] = c[nb][3] = 0.f;
            #pragma unroll
            for (int kc = 0; kc < 2; kc++) {
                uint b0 = sK2[cur][(8 * kc + tig)     * KS2 + nb * 8 + g];
                uint b1 = sK2[cur][(8 * kc + tig + 4) * KS2 + nb * 8 + g];
                mma_f16(c[nb], qa[kc][0], qa[kc][1], qa[kc][2], qa[kc][3], b0, b1);
            }
        }

        // ---- fused bias + exp2 + pack + PV per 16-key chunk ----
        #pragma unroll
        for (int kc = 0; kc < 4; kc++) {
            const int nb0 = 2 * kc, nb1 = 2 * kc + 1;
            float2 lb0 = *(const float2*)&g_Lq[t * 64 + nb0 * 8 + 2 * tig];
            float2 lb1 = *(const float2*)&g_Lq[t * 64 + nb1 * 8 + 2 * tig];
            float p00 = ex2(c[nb0][0] + lb0.x);
            float p01 = ex2(c[nb0][1] + lb0.y);
            float p02 = ex2(c[nb0][2] + lb0.x);
            float p03 = ex2(c[nb0][3] + lb0.y);
            float p10 = ex2(c[nb1][0] + lb1.x);
            float p11 = ex2(c[nb1][1] + lb1.y);
            float p12 = ex2(c[nb1][2] + lb1.x);
            float p13 = ex2(c[nb1][3] + lb1.y);
            l0 += (p00 + p01) + (p10 + p11);
            l1 += (p02 + p03) + (p12 + p13);
            // fp16 A-fragment == C-fragment pairs
            uint pa0 = packh2(p00, p01);
            uint pa1 = packh2(p02, p03);
            uint pa2 = packh2(p10, p11);
            uint pa3 = packh2(p12, p13);
            const int kp0 = 8 * kc + tig;       // key-pair index for b0
            #pragma unroll
            for (int db = 0; db < 4; db++) {
                uint b0 = sV[cur][(db * 8 + g) * VS2 + kp0];
                uint b1 = sV[cur][(db * 8 + g) * VS2 + kp0 + 4];
                mma_f16(o[db], pa0, pa1, pa2, pa3, b0, b1);
            }
        }

        // ---- store next tile into the other buffer ----
        if (more) {
            if (tid < 256) {
                uint4 kk;
                kk.x = packh2(rka.x, rkb.x);
                kk.y = packh2(rka.y, rkb.y);
                kk.z = packh2(rka.z, rkb.z);
                kk.w = packh2(rka.w, rkb.w);
                *(uint4*)&sK2[nxt][fdp * KS2 + fkc * 4] = kk;
            }
            uint2 vv;
            vv.x = packh2(rva.x, rva.y);
            vv.y = packh2(rva.z, rva.w);
            *(uint2*)&sV[nxt][fdp * VS2 + fkc * 2] = vv;
        }
        __syncthreads();
    }

    // ---- final lane-quad reduction of l, then pre-split epilogue ----
    l0 += __shfl_xor_sync(0xffffffffu, l0, 1);
    l0 += __shfl_xor_sync(0xffffffffu, l0, 2);
    l1 += __shfl_xor_sync(0xffffffffu, l1, 1);
    l1 += __shfl_xor_sync(0xffffffffu, l1, 2);
    float inv0 = 1.f / l0;
    float inv1 = 1.f / l1;
    #pragma unroll
    for (int db = 0; db < 4; db++) {
        int d = db * 8 + 2 * tig;
        if (q_row0 < NPIX) {
            g_Os[(h * DHEAD + d)     * NPIX + q_row0] = split2(o[db][0] * inv0);
            g_Os[(h * DHEAD + d + 1) * NPIX + q_row0] = split2(o[db][1] * inv0);
        }
        if (q_row1 < NPIX) {
            g_Os[(h * DHEAD + d)     * NPIX + q_row1] = split2(o[db][2] * inv1);
            g_Os[(h * DHEAD + d + 1) * NPIX + q_row1] = split2(o[db][3] * inv1);
        }
    }
}

// ============================================================================
extern "C" void kernel_launch(void* const* d_in, const int* in_sizes, int n_in,
                              void* d_out, int out_size)
{
    const float* query = (const float*)d_in[0];
    const float* q_w   = (const float*)d_in[1];
    const float* q_b   = (const float*)d_in[2];
    const float* k_w   = (const float*)d_in[3];
    const float* k_b   = (const float*)d_in[4];
    const float* v_w   = (const float*)d_in[5];
    const float* v_b   = (const float*)d_in[6];
    const float* p_w   = (const float*)d_in[7];
    const float* p_b   = (const float*)d_in[8];
    const float* lqw   = (const float*)d_in[9];
    float* out = (float*)d_out;

    cudaFuncSetAttribute(gemm_qkv,  cudaFuncAttributeMaxDynamicSharedMemorySize, GSMEM_BYTES);
    cudaFuncSetAttribute(gemm_proj, cudaFuncAttributeMaxDynamicSharedMemorySize, GSMEM_BYTES);

    split_x<<<(NX_TOT + 255) / 256, 256>>>(query);

    dim3 gq((NPIX + 127) / 128, 4, 3);                     // 33 x 4 x 3
    gemm_qkv<<<gq, 256, GSMEM_BYTES>>>(q_w, q_b, k_w, k_b, v_w, v_b, lqw);

    dim3 ga((NPIX + 255) / 256, HEADS, 1);                 // 17 x 8 = 136
    attn_kernel<<<ga, 512>>>();                            // -> g_Os (pre-split)

    dim3 gp((NPIX + 127) / 128, 4, 1);                     // 33 x 4
    gemm_proj<<<gp, 256, GSMEM_BYTES>>>(p_w, p_b, out);
}

// round 12
// speedup vs baseline: 1.3133x; 1.1213x over previous
#include <cuda_runtime.h>
#include <cuda_fp16.h>
#include <math.h>

#define NPIX 4140      // 46*90
#define CIN  256
#define HEADS 8
#define DHEAD 32
#define NTK  65        // key tiles of 64 (65*64 = 4160)
#define LOG2E 1.4426950408889634f
#define NCP  (CIN / 2)              // 128 c-pairs

typedef unsigned int uint;

// ---------------- scratch (no allocations allowed) ----------------
__device__ float g_Q[CIN * NPIX];
__device__ float g_K[CIN * NPIX];
__device__ float g_V[CIN * NPIX];
__device__ uint  g_Oh2[NCP * NPIX];     // attn out, fp16 hi pairs [cp][n]
__device__ uint  g_Ol2[NCP * NPIX];     // attn out, fp16 lo pairs
__device__ uint  g_Xh2[NCP * NPIX];     // query,  fp16 hi pairs [cp][n]
__device__ uint  g_Xl2[NCP * NPIX];     // query,  fp16 lo pairs
__device__ uint  g_Wh2[4 * CIN * NCP];  // q,k,v,p weights hi pairs [k][cp]
__device__ uint  g_Wl2[4 * CIN * NCP];  // weights lo pairs
__device__ float g_Lq[NTK * 64];        // log-quad bias * log2(e), padded

// ---------------- helpers ----------------
__device__ __forceinline__ float ex2(float x) {
    float y;
    asm("ex2.approx.f32 %0, %1;" : "=f"(y) : "f"(x));
    return y;
}

__device__ __forceinline__ uint packh2(float a, float b) {
    // half2: low = a, high = b (round-to-nearest)
    uint r;
    asm("cvt.rn.f16x2.f32 %0, %2, %1;" : "=r"(r) : "f"(a), "f"(b));
    return r;
}

__device__ __forceinline__ float2 unpackh2(uint u) {
    __half2 h = *reinterpret_cast<__half2*>(&u);
    return make_float2(__low2float(h), __high2float(h));
}

// pack (a,b) into fp16 hi pair + fp16 lo (residual) pair
__device__ __forceinline__ void split_pair(float a, float b, uint& hi, uint& lo) {
    hi = packh2(a, b);
    float2 hv = unpackh2(hi);
    lo = packh2(a - hv.x, b - hv.y);
}

__device__ __forceinline__ void mma_f16(float c[4],
                                        uint a0, uint a1, uint a2, uint a3,
                                        uint b0, uint b1) {
    asm volatile(
        "mma.sync.aligned.m16n8k16.row.col.f32.f16.f16.f32 "
        "{%0,%1,%2,%3}, {%4,%5,%6,%7}, {%8,%9}, {%0,%1,%2,%3};"
        : "+f"(c[0]), "+f"(c[1]), "+f"(c[2]), "+f"(c[3])
        : "r"(a0), "r"(a1), "r"(a2), "r"(a3), "r"(b0), "r"(b1));
}

__device__ __forceinline__ void cp_async16(void* dst, const void* src, int src_sz) {
    uint d = (uint)__cvta_generic_to_shared(dst);
    asm volatile("cp.async.cg.shared.global [%0], [%1], 16, %2;"
                 :: "r"(d), "l"(src), "r"(src_sz));
}
__device__ __forceinline__ void cp_commit() { asm volatile("cp.async.commit_group;"); }
__device__ __forceinline__ void cp_wait0()  { asm volatile("cp.async.wait_group 0;"); }

// ============================================================================
// Pre-split weights -> g_Wh2/g_Wl2 (fp16 c-pair packed)
// ============================================================================
#define NWP_TOT (4 * CIN * NCP)        // 131072 pair entries

__global__ __launch_bounds__(256)
void split_w(const float* __restrict__ qw, const float* __restrict__ kw,
             const float* __restrict__ vw, const float* __restrict__ pw)
{
    int i = blockIdx.x * 256 + threadIdx.x;
    if (i >= NWP_TOT) return;
    int m   = i >> 15;                 // 32768 pairs per matrix
    int rem = i & 32767;
    int k   = rem >> 7;
    int cp  = rem & 127;
    const float* W = (m == 0) ? qw : (m == 1) ? kw : (m == 2) ? vw : pw;
    float a = W[k * CIN + 2 * cp];
    float b = W[k * CIN + 2 * cp + 1];
    uint hi, lo;
    split_pair(a, b, hi, lo);
    g_Wh2[i] = hi;
    g_Wl2[i] = lo;
}

// ============================================================================
// Pre-split query -> g_Xh2/g_Xl2 (fp16 c-pair packed, [cp][n])
// ============================================================================
__global__ __launch_bounds__(256)
void split_x(const float* __restrict__ query)
{
    int cp = blockIdx.y;
    int n  = blockIdx.x * 256 + threadIdx.x;
    if (n >= NPIX) return;
    float a = query[(2 * cp)     * NPIX + n];
    float b = query[(2 * cp + 1) * NPIX + n];
    uint hi, lo;
    split_pair(a, b, hi, lo);
    g_Xh2[cp * NPIX + n] = hi;
    g_Xl2[cp * NPIX + n] = lo;
}

// ============================================================================
// 3-term fp16-split GEMM (hh + hl + lh), m16n8k16, pre-split operands.
// Tile 64k x 64n, 128 thr / 4 warps (warp w -> rows k0+16w..+15). k-step 32
// (16 c-pairs). cp.async double-buffered, one sync per k-step. ~39 KB smem.
// ============================================================================
#define WST 20     // uints per W row (16 cp + pad); banks 20g+tig distinct
#define XST 72     // uints per X cp-row (64 n + pad); banks 8tig+g distinct

__device__ __forceinline__
void gemm_core(const uint* __restrict__ Xh2, const uint* __restrict__ Xl2,
               const uint* __restrict__ Wh2, const uint* __restrict__ Wl2,
               const float* __restrict__ bias, float* __restrict__ Y)
{
    __shared__ uint sWh[2][64 * WST], sWl[2][64 * WST];
    __shared__ uint sXh[2][16 * XST], sXl[2][16 * XST];

    const int tid  = threadIdx.x;
    const int w    = tid >> 5;
    const int lane = tid & 31;
    const int g    = lane >> 2;
    const int tig  = lane & 3;
    const int k0   = blockIdx.y * 64;
    const int n0   = blockIdx.x * 64;

    // ---- prologue: stage 0 (cc2 = 0) ----
    {
        #pragma unroll
        for (int r = 0; r < 2; r++) {              // W: 64 rows x 16 cp
            int idx = tid + 128 * r;
            int wk = idx >> 2, wcp = (idx & 3) * 4;
            cp_async16(&sWh[0][wk * WST + wcp], &Wh2[(k0 + wk) * NCP + wcp], 16);
            cp_async16(&sWl[0][wk * WST + wcp], &Wl2[(k0 + wk) * NCP + wcp], 16);
        }
        #pragma unroll
        for (int r = 0; r < 2; r++) {              // X: 16 cp x 64 n
            int idx = tid + 128 * r;
            int xcp = idx >> 4, xn = (idx & 15) * 4;
            int n = n0 + xn;
            int ok = (n < NPIX);
            cp_async16(&sXh[0][xcp * XST + xn], &Xh2[xcp * NPIX + (ok ? n : 0)], ok ? 16 : 0);
            cp_async16(&sXl[0][xcp * XST + xn], &Xl2[xcp * NPIX + (ok ? n : 0)], ok ? 16 : 0);
        }
        cp_commit();
    }

    float acc[8][4];
    #pragma unroll
    for (int nb = 0; nb < 8; nb++)
        #pragma unroll
        for (int i = 0; i < 4; i++) acc[nb][i] = 0.f;

    cp_wait0();
    __syncthreads();

    #pragma unroll
    for (int it = 0; it < 8; it++) {
        const int cur = it & 1;
        const int nxt = cur ^ 1;
        const bool more = (it + 1 < 8);

        // ---- issue next stage copies ----
        if (more) {
            const int cc2 = (it + 1) * 16;         // c-pair base
            #pragma unroll
            for (int r = 0; r < 2; r++) {
                int idx = tid + 128 * r;
                int wk = idx >> 2, wcp = (idx & 3) * 4;
                cp_async16(&sWh[nxt][wk * WST + wcp],
                           &Wh2[(k0 + wk) * NCP + cc2 + wcp], 16);
                cp_async16(&sWl[nxt][wk * WST + wcp],
                           &Wl2[(k0 + wk) * NCP + cc2 + wcp], 16);
            }
            #pragma unroll
            for (int r = 0; r < 2; r++) {
                int idx = tid + 128 * r;
                int xcp = idx >> 4, xn = (idx & 15) * 4;
                int n = n0 + xn;
                int ok = (n < NPIX);
                cp_async16(&sXh[nxt][xcp * XST + xn],
                           &Xh2[(cc2 + xcp) * NPIX + (ok ? n : 0)], ok ? 16 : 0);
                cp_async16(&sXl[nxt][xcp * XST + xn],
                           &Xl2[(cc2 + xcp) * NPIX + (ok ? n : 0)], ok ? 16 : 0);
            }
            cp_commit();
        }

        // ---- compute: 2 k16 chunks x 8 nb x 3 terms ----
        #pragma unroll
        for (int kb = 0; kb < 2; kb++) {
            const int ar = (w * 16 + g) * WST + kb * 8 + tig;
            uint ah0 = sWh[cur][ar];
            uint ah1 = sWh[cur][ar + 8 * WST];
            uint ah2 = sWh[cur][ar + 4];
            uint ah3 = sWh[cur][ar + 8 * WST + 4];
            uint al0 = sWl[cur][ar];
            uint al1 = sWl[cur][ar + 8 * WST];
            uint al2 = sWl[cur][ar + 4];
            uint al3 = sWl[cur][ar + 8 * WST + 4];
            const int br0 = (kb * 8 + tig) * XST + g;
            const int br1 = br0 + 4 * XST;
            #pragma unroll
            for (int nb = 0; nb < 8; nb++) {
                uint bh0 = sXh[cur][br0 + nb * 8];
                uint bh1 = sXh[cur][br1 + nb * 8];
                uint bl0 = sXl[cur][br0 + nb * 8];
                uint bl1 = sXl[cur][br1 + nb * 8];
                mma_f16(acc[nb], ah0, ah1, ah2, ah3, bh0, bh1);
                mma_f16(acc[nb], ah0, ah1, ah2, ah3, bl0, bl1);
                mma_f16(acc[nb], al0, al1, al2, al3, bh0, bh1);
            }
        }

        if (more) cp_wait0();
        __syncthreads();
    }

    const int r0 = k0 + w * 16 + g;
    const int r1 = r0 + 8;
    const float bv0 = __ldg(&bias[r0]);
    const float bv1 = __ldg(&bias[r1]);
    #pragma unroll
    for (int nb = 0; nb < 8; nb++) {
        int n = n0 + nb * 8 + 2 * tig;
        if (n < NPIX) {
            float2 y0 = make_float2(acc[nb][0] + bv0, acc[nb][1] + bv0);
            float2 y1 = make_float2(acc[nb][2] + bv1, acc[nb][3] + bv1);
            *(float2*)&Y[r0 * NPIX + n] = y0;
            *(float2*)&Y[r1 * NPIX + n] = y1;
        }
    }
}

__global__ __launch_bounds__(128)
void gemm_qkv(const float* __restrict__ qb, const float* __restrict__ kb,
              const float* __restrict__ vb, const float* __restrict__ lq)
{
    int z = blockIdx.z;
    if (z == 0 && blockIdx.x == 0 && blockIdx.y == 0) {
        for (int i = threadIdx.x; i < NTK * 64; i += 128)
            g_Lq[i] = (i < NPIX) ? lq[i] * LOG2E : -1e30f;
    }
    const float* B = (z == 0) ? qb : (z == 1) ? kb : vb;
    float* Y       = (z == 0) ? g_Q : (z == 1) ? g_K : g_V;
    gemm_core(g_Xh2, g_Xl2, g_Wh2 + z * CIN * NCP, g_Wl2 + z * CIN * NCP, B, Y);
}

__global__ __launch_bounds__(128)
void gemm_proj(const float* __restrict__ B, float* __restrict__ Y)
{
    gemm_core(g_Oh2, g_Ol2, g_Wh2 + 3 * CIN * NCP, g_Wl2 + 3 * CIN * NCP, B, Y);
}

// ============================================================================
// Flash attention, fp16 m16n8k16 mma.sync (fp32 accumulate), fixed-shift
// base-2 softmax (scores <= ~0 with huge margin; shift-invariance => exact).
//   Block: 512 threads / 16 warps, 256 queries -> grid 17 x 8 = one wave.
//   sK2: [16 d-pairs][64 keys] half2; sV: [32 d][32 key-pairs] half2.
//   P's fp16 A-fragment == S's C-fragment pairs (no shuffles).
//   Epilogue writes g_Oh2/g_Ol2 fp16-split c-pairs for the projection GEMM.
// ============================================================================
#define KS2 72     // uints per dp row (288 B)
#define VS2 36     // uints per d row  (144 B)

__global__ __launch_bounds__(512)
void attn_kernel()
{
    __shared__ uint sK2[2][16 * KS2];
    __shared__ uint sV [2][32 * VS2];

    const int tid  = threadIdx.x;
    const int lane = tid & 31;
    const int w    = tid >> 5;
    const int g    = lane >> 2;
    const int tig  = lane & 3;
    const int h    = blockIdx.y;
    const int qb   = blockIdx.x;

    const int q_row0 = qb * 256 + w * 16 + g;
    const int q_row1 = q_row0 + 8;

    // fill roles
    const int fdp = tid >> 4;           // K: d-pair 0..15 (tid<256); V: d 0..31
    const int fkc = tid & 15;           // key chunk of 4

    // ---- Q fragments, fp16 (scale includes log2 e) ----
    const float scale = 0.17677669529663687f * LOG2E;
    const int r0 = (q_row0 < NPIX) ? q_row0 : (NPIX - 1);
    const int r1 = (q_row1 < NPIX) ? q_row1 : (NPIX - 1);
    uint qa[2][4];
    #pragma unroll
    for (int kc = 0; kc < 2; kc++) {
        int d0 = kc * 16 + 2 * tig;
        const float* Qh = g_Q + (size_t)h * DHEAD * NPIX;
        qa[kc][0] = packh2(Qh[(d0)     * NPIX + r0] * scale, Qh[(d0 + 1) * NPIX + r0] * scale);
        qa[kc][1] = packh2(Qh[(d0)     * NPIX + r1] * scale, Qh[(d0 + 1) * NPIX + r1] * scale);
        qa[kc][2] = packh2(Qh[(d0 + 8) * NPIX + r0] * scale, Qh[(d0 + 9) * NPIX + r0] * scale);
        qa[kc][3] = packh2(Qh[(d0 + 8) * NPIX + r1] * scale, Qh[(d0 + 9) * NPIX + r1] * scale);
    }

    float o[4][4];
    #pragma unroll
    for (int db = 0; db < 4; db++)
        #pragma unroll
        for (int j = 0; j < 4; j++) o[db][j] = 0.f;

    float l0 = 0.f, l1 = 0.f;
    float4 rka, rkb, rva;

    const float* Kbase = g_K + (size_t)h * DHEAD * NPIX;
    const float* Vbase = g_V + (size_t)h * DHEAD * NPIX;

    // ---------- prologue: load + store tile 0 ----------
    {
        int key0 = fkc * 4;             // t = 0, always valid
        if (tid < 256) {
            rka = *(const float4*)&Kbase[(2 * fdp)     * NPIX + key0];
            rkb = *(const float4*)&Kbase[(2 * fdp + 1) * NPIX + key0];
            uint4 kk;
            kk.x = packh2(rka.x, rkb.x);
            kk.y = packh2(rka.y, rkb.y);
            kk.z = packh2(rka.z, rkb.z);
            kk.w = packh2(rka.w, rkb.w);
            *(uint4*)&sK2[0][fdp * KS2 + key0] = kk;
        }
        rva = *(const float4*)&Vbase[fdp * NPIX + key0];   // V role: fdp = d (0..31)
        uint2 vv;
        vv.x = packh2(rva.x, rva.y);
        vv.y = packh2(rva.z, rva.w);
        *(uint2*)&sV[0][fdp * VS2 + fkc * 2] = vv;
    }
    __syncthreads();

    for (int t = 0; t < NTK; t++) {
        const int cur = t & 1;
        const int nxt = cur ^ 1;
        const bool more = (t + 1 < NTK);

        // ---- issue next-tile global loads into registers ----
        if (more) {
            int key0 = (t + 1) * 64 + fkc * 4;
            bool ok = (key0 < NPIX);        // NPIX % 4 == 0 -> full float4
            int keyc = ok ? key0 : 0;
            if (tid < 256) {
                float4 ka = *(const float4*)&Kbase[(2 * fdp)     * NPIX + keyc];
                float4 kb = *(const float4*)&Kbase[(2 * fdp + 1) * NPIX + keyc];
                rka = ok ? ka : make_float4(0.f, 0.f, 0.f, 0.f);
                rkb = ok ? kb : make_float4(0.f, 0.f, 0.f, 0.f);
            }
            float4 va = *(const float4*)&Vbase[fdp * NPIX + keyc];
            rva = ok ? va : make_float4(0.f, 0.f, 0.f, 0.f);
        }

        // ---- S = Q K^T : 8 nb x 2 kc of m16n8k16 ----
        float c[8][4];
        #pragma unroll
        for (int nb = 0; nb < 8; nb++) {
            c[nb][0] = c[nb][1] = c[nb][2] = c[nb][3] = 0.f;
            #pragma unroll
            for (int kc = 0; kc < 2; kc++) {
                uint b0 = sK2[cur][(8 * kc + tig)     * KS2 + nb * 8 + g];
                uint b1 = sK2[cur][(8 * kc + tig + 4) * KS2 + nb * 8 + g];
                mma_f16(c[nb], qa[kc][0], qa[kc][1], qa[kc][2], qa[kc][3], b0, b1);
            }
        }

        // ---- fused bias + exp2 + pack + PV per 16-key chunk ----
        #pragma unroll
        for (int kc = 0; kc < 4; kc++) {
            const int nb0 = 2 * kc, nb1 = 2 * kc + 1;
            float2 lb0 = *(const float2*)&g_Lq[t * 64 + nb0 * 8 + 2 * tig];
            float2 lb1 = *(const float2*)&g_Lq[t * 64 + nb1 * 8 + 2 * tig];
            float p00 = ex2(c[nb0][0] + lb0.x);
            float p01 = ex2(c[nb0][1] + lb0.y);
            float p02 = ex2(c[nb0][2] + lb0.x);
            float p03 = ex2(c[nb0][3] + lb0.y);
            float p10 = ex2(c[nb1][0] + lb1.x);
            float p11 = ex2(c[nb1][1] + lb1.y);
            float p12 = ex2(c[nb1][2] + lb1.x);
            float p13 = ex2(c[nb1][3] + lb1.y);
            l0 += (p00 + p01) + (p10 + p11);
            l1 += (p02 + p03) + (p12 + p13);
            uint pa0 = packh2(p00, p01);
            uint pa1 = packh2(p02, p03);
            uint pa2 = packh2(p10, p11);
            uint pa3 = packh2(p12, p13);
            const int kp0 = 8 * kc + tig;
            #pragma unroll
            for (int db = 0; db < 4; db++) {
                uint b0 = sV[cur][(db * 8 + g) * VS2 + kp0];
                uint b1 = sV[cur][(db * 8 + g) * VS2 + kp0 + 4];
                mma_f16(o[db], pa0, pa1, pa2, pa3, b0, b1);
            }
        }

        // ---- store next tile into the other buffer ----
        if (more) {
            if (tid < 256) {
                uint4 kk;
                kk.x = packh2(rka.x, rkb.x);
                kk.y = packh2(rka.y, rkb.y);
                kk.z = packh2(rka.z, rkb.z);
                kk.w = packh2(rka.w, rkb.w);
                *(uint4*)&sK2[nxt][fdp * KS2 + fkc * 4] = kk;
            }
            uint2 vv;
            vv.x = packh2(rva.x, rva.y);
            vv.y = packh2(rva.z, rva.w);
            *(uint2*)&sV[nxt][fdp * VS2 + fkc * 2] = vv;
        }
        __syncthreads();
    }

    // ---- final lane-quad reduction of l, then fp16-split epilogue ----
    l0 += __shfl_xor_sync(0xffffffffu, l0, 1);
    l0 += __shfl_xor_sync(0xffffffffu, l0, 2);
    l1 += __shfl_xor_sync(0xffffffffu, l1, 1);
    l1 += __shfl_xor_sync(0xffffffffu, l1, 2);
    float inv0 = 1.f / l0;
    float inv1 = 1.f / l1;
    #pragma unroll
    for (int db = 0; db < 4; db++) {
        int cpg = h * 16 + db * 4 + tig;       // global c-pair index
        if (q_row0 < NPIX) {
            uint hi, lo;
            split_pair(o[db][0] * inv0, o[db][1] * inv0, hi, lo);
            g_Oh2[cpg * NPIX + q_row0] = hi;
            g_Ol2[cpg * NPIX + q_row0] = lo;
        }
        if (q_row1 < NPIX) {
            uint hi, lo;
            split_pair(o[db][2] * inv1, o[db][3] * inv1, hi, lo);
            g_Oh2[cpg * NPIX + q_row1] = hi;
            g_Ol2[cpg * NPIX + q_row1] = lo;
        }
    }
}

// ============================================================================
extern "C" void kernel_launch(void* const* d_in, const int* in_sizes, int n_in,
                              void* d_out, int out_size)
{
    const float* query = (const float*)d_in[0];
    const float* q_w   = (const float*)d_in[1];
    const float* q_b   = (const float*)d_in[2];
    const float* k_w   = (const float*)d_in[3];
    const float* k_b   = (const float*)d_in[4];
    const float* v_w   = (const float*)d_in[5];
    const float* v_b   = (const float*)d_in[6];
    const float* p_w   = (const float*)d_in[7];
    const float* p_b   = (const float*)d_in[8];
    const float* lqw   = (const float*)d_in[9];
    float* out = (float*)d_out;

    split_w<<<(NWP_TOT + 255) / 256, 256>>>(q_w, k_w, v_w, p_w);

    dim3 gx((NPIX + 255) / 256, NCP, 1);
    split_x<<<gx, 256>>>(query);

    dim3 gq((NPIX + 63) / 64, 4, 3);                       // 65 x 4 x 3 = 780
    gemm_qkv<<<gq, 128>>>(q_b, k_b, v_b, lqw);

    dim3 ga((NPIX + 255) / 256, HEADS, 1);                 // 17 x 8 = 136
    attn_kernel<<<ga, 512>>>();                            // -> g_Oh2/g_Ol2

    dim3 gp((NPIX + 63) / 64, 4, 1);                       // 65 x 4 = 260
    gemm_proj<<<gp, 128>>>(p_b, out);
}

// round 13
// speedup vs baseline: 1.5369x; 1.1703x over previous
#include <cuda_runtime.h>
#include <cuda_fp16.h>
#include <math.h>

#define NPIX 4140      // 46*90
#define CIN  256
#define HEADS 8
#define DHEAD 32
#define NTK  65        // key tiles of 64 (65*64 = 4160)
#define NSPLIT 2
#define TSPL 33        // tiles per split (ceil(65/2))
#define LOG2E 1.4426950408889634f
#define NCP  (CIN / 2)              // 128 c-pairs

typedef unsigned int uint;

// ---------------- scratch (no allocations allowed) ----------------
__device__ float g_Q[CIN * NPIX];
__device__ float g_K[CIN * NPIX];
__device__ float g_V[CIN * NPIX];
__device__ float g_Po[NSPLIT][HEADS * NPIX * DHEAD];  // unnormalized o partials [h][q][d]
__device__ float g_Pl[NSPLIT][HEADS * NPIX];          // partial l
__device__ uint  g_Oh2[NCP * NPIX];     // attn out, fp16 hi pairs [cp][n]
__device__ uint  g_Ol2[NCP * NPIX];     // attn out, fp16 lo pairs
__device__ uint  g_Xh2[NCP * NPIX];     // query,  fp16 hi pairs [cp][n]
__device__ uint  g_Xl2[NCP * NPIX];     // query,  fp16 lo pairs
__device__ uint  g_Wh2[4 * CIN * NCP];  // q,k,v,p weights hi pairs [k][cp]
__device__ uint  g_Wl2[4 * CIN * NCP];  // weights lo pairs
__device__ float g_Lq[NTK * 64];        // log-quad bias * log2(e), padded

// ---------------- helpers ----------------
__device__ __forceinline__ float ex2(float x) {
    float y;
    asm("ex2.approx.f32 %0, %1;" : "=f"(y) : "f"(x));
    return y;
}

__device__ __forceinline__ uint packh2(float a, float b) {
    uint r;
    asm("cvt.rn.f16x2.f32 %0, %2, %1;" : "=r"(r) : "f"(a), "f"(b));
    return r;
}

__device__ __forceinline__ float2 unpackh2(uint u) {
    __half2 h = *reinterpret_cast<__half2*>(&u);
    return make_float2(__low2float(h), __high2float(h));
}

__device__ __forceinline__ void split_pair(float a, float b, uint& hi, uint& lo) {
    hi = packh2(a, b);
    float2 hv = unpackh2(hi);
    lo = packh2(a - hv.x, b - hv.y);
}

__device__ __forceinline__ void mma_f16(float c[4],
                                        uint a0, uint a1, uint a2, uint a3,
                                        uint b0, uint b1) {
    asm volatile(
        "mma.sync.aligned.m16n8k16.row.col.f32.f16.f16.f32 "
        "{%0,%1,%2,%3}, {%4,%5,%6,%7}, {%8,%9}, {%0,%1,%2,%3};"
        : "+f"(c[0]), "+f"(c[1]), "+f"(c[2]), "+f"(c[3])
        : "r"(a0), "r"(a1), "r"(a2), "r"(a3), "r"(b0), "r"(b1));
}

__device__ __forceinline__ void cp_async16(void* dst, const void* src, int src_sz) {
    uint d = (uint)__cvta_generic_to_shared(dst);
    asm volatile("cp.async.cg.shared.global [%0], [%1], 16, %2;"
                 :: "r"(d), "l"(src), "r"(src_sz));
}
__device__ __forceinline__ void cp_commit() { asm volatile("cp.async.commit_group;"); }
__device__ __forceinline__ void cp_wait0()  { asm volatile("cp.async.wait_group 0;"); }

// ============================================================================
// Pre-split weights -> g_Wh2/g_Wl2 (fp16 c-pair packed)
// ============================================================================
#define NWP_TOT (4 * CIN * NCP)        // 131072 pair entries

__global__ __launch_bounds__(256)
void split_w(const float* __restrict__ qw, const float* __restrict__ kw,
             const float* __restrict__ vw, const float* __restrict__ pw)
{
    int i = blockIdx.x * 256 + threadIdx.x;
    if (i >= NWP_TOT) return;
    int m   = i >> 15;
    int rem = i & 32767;
    int k   = rem >> 7;
    int cp  = rem & 127;
    const float* W = (m == 0) ? qw : (m == 1) ? kw : (m == 2) ? vw : pw;
    float a = W[k * CIN + 2 * cp];
    float b = W[k * CIN + 2 * cp + 1];
    uint hi, lo;
    split_pair(a, b, hi, lo);
    g_Wh2[i] = hi;
    g_Wl2[i] = lo;
}

// ============================================================================
// Pre-split query -> g_Xh2/g_Xl2 (fp16 c-pair packed, [cp][n])
// ============================================================================
__global__ __launch_bounds__(256)
void split_x(const float* __restrict__ query)
{
    int cp = blockIdx.y;
    int n  = blockIdx.x * 256 + threadIdx.x;
    if (n >= NPIX) return;
    float a = query[(2 * cp)     * NPIX + n];
    float b = query[(2 * cp + 1) * NPIX + n];
    uint hi, lo;
    split_pair(a, b, hi, lo);
    g_Xh2[cp * NPIX + n] = hi;
    g_Xl2[cp * NPIX + n] = lo;
}

// ============================================================================
// 3-term fp16-split GEMM (hh + hl + lh), m16n8k16, pre-split operands.
// Tile 64k x 64n, 128 thr / 4 warps. k-step 32 (16 c-pairs), double-buffered.
// ============================================================================
#define WST 20
#define XST 72

__device__ __forceinline__
void gemm_core(const uint* __restrict__ Xh2, const uint* __restrict__ Xl2,
               const uint* __restrict__ Wh2, const uint* __restrict__ Wl2,
               const float* __restrict__ bias, float* __restrict__ Y)
{
    __shared__ uint sWh[2][64 * WST], sWl[2][64 * WST];
    __shared__ uint sXh[2][16 * XST], sXl[2][16 * XST];

    const int tid  = threadIdx.x;
    const int w    = tid >> 5;
    const int lane = tid & 31;
    const int g    = lane >> 2;
    const int tig  = lane & 3;
    const int k0   = blockIdx.y * 64;
    const int n0   = blockIdx.x * 64;

    {
        #pragma unroll
        for (int r = 0; r < 2; r++) {
            int idx = tid + 128 * r;
            int wk = idx >> 2, wcp = (idx & 3) * 4;
            cp_async16(&sWh[0][wk * WST + wcp], &Wh2[(k0 + wk) * NCP + wcp], 16);
            cp_async16(&sWl[0][wk * WST + wcp], &Wl2[(k0 + wk) * NCP + wcp], 16);
        }
        #pragma unroll
        for (int r = 0; r < 2; r++) {
            int idx = tid + 128 * r;
            int xcp = idx >> 4, xn = (idx & 15) * 4;
            int n = n0 + xn;
            int ok = (n < NPIX);
            cp_async16(&sXh[0][xcp * XST + xn], &Xh2[xcp * NPIX + (ok ? n : 0)], ok ? 16 : 0);
            cp_async16(&sXl[0][xcp * XST + xn], &Xl2[xcp * NPIX + (ok ? n : 0)], ok ? 16 : 0);
        }
        cp_commit();
    }

    float acc[8][4];
    #pragma unroll
    for (int nb = 0; nb < 8; nb++)
        #pragma unroll
        for (int i = 0; i < 4; i++) acc[nb][i] = 0.f;

    cp_wait0();
    __syncthreads();

    #pragma unroll
    for (int it = 0; it < 8; it++) {
        const int cur = it & 1;
        const int nxt = cur ^ 1;
        const bool more = (it + 1 < 8);

        if (more) {
            const int cc2 = (it + 1) * 16;
            #pragma unroll
            for (int r = 0; r < 2; r++) {
                int idx = tid + 128 * r;
                int wk = idx >> 2, wcp = (idx & 3) * 4;
                cp_async16(&sWh[nxt][wk * WST + wcp],
                           &Wh2[(k0 + wk) * NCP + cc2 + wcp], 16);
                cp_async16(&sWl[nxt][wk * WST + wcp],
                           &Wl2[(k0 + wk) * NCP + cc2 + wcp], 16);
            }
            #pragma unroll
            for (int r = 0; r < 2; r++) {
                int idx = tid + 128 * r;
                int xcp = idx >> 4, xn = (idx & 15) * 4;
                int n = n0 + xn;
                int ok = (n < NPIX);
                cp_async16(&sXh[nxt][xcp * XST + xn],
                           &Xh2[(cc2 + xcp) * NPIX + (ok ? n : 0)], ok ? 16 : 0);
                cp_async16(&sXl[nxt][xcp * XST + xn],
                           &Xl2[(cc2 + xcp) * NPIX + (ok ? n : 0)], ok ? 16 : 0);
            }
            cp_commit();
        }

        #pragma unroll
        for (int kb = 0; kb < 2; kb++) {
            const int ar = (w * 16 + g) * WST + kb * 8 + tig;
            uint ah0 = sWh[cur][ar];
            uint ah1 = sWh[cur][ar + 8 * WST];
            uint ah2 = sWh[cur][ar + 4];
            uint ah3 = sWh[cur][ar + 8 * WST + 4];
            uint al0 = sWl[cur][ar];
            uint al1 = sWl[cur][ar + 8 * WST];
            uint al2 = sWl[cur][ar + 4];
            uint al3 = sWl[cur][ar + 8 * WST + 4];
            const int br0 = (kb * 8 + tig) * XST + g;
            const int br1 = br0 + 4 * XST;
            #pragma unroll
            for (int nb = 0; nb < 8; nb++) {
                uint bh0 = sXh[cur][br0 + nb * 8];
                uint bh1 = sXh[cur][br1 + nb * 8];
                uint bl0 = sXl[cur][br0 + nb * 8];
                uint bl1 = sXl[cur][br1 + nb * 8];
                mma_f16(acc[nb], ah0, ah1, ah2, ah3, bh0, bh1);
                mma_f16(acc[nb], ah0, ah1, ah2, ah3, bl0, bl1);
                mma_f16(acc[nb], al0, al1, al2, al3, bh0, bh1);
            }
        }

        if (more) cp_wait0();
        __syncthreads();
    }

    const int r0 = k0 + w * 16 + g;
    const int r1 = r0 + 8;
    const float bv0 = __ldg(&bias[r0]);
    const float bv1 = __ldg(&bias[r1]);
    #pragma unroll
    for (int nb = 0; nb < 8; nb++) {
        int n = n0 + nb * 8 + 2 * tig;
        if (n < NPIX) {
            float2 y0 = make_float2(acc[nb][0] + bv0, acc[nb][1] + bv0);
            float2 y1 = make_float2(acc[nb][2] + bv1, acc[nb][3] + bv1);
            *(float2*)&Y[r0 * NPIX + n] = y0;
            *(float2*)&Y[r1 * NPIX + n] = y1;
        }
    }
}

__global__ __launch_bounds__(128)
void gemm_qkv(const float* __restrict__ qb, const float* __restrict__ kb,
              const float* __restrict__ vb, const float* __restrict__ lq)
{
    int z = blockIdx.z;
    if (z == 0 && blockIdx.x == 0 && blockIdx.y == 0) {
        for (int i = threadIdx.x; i < NTK * 64; i += 128)
            g_Lq[i] = (i < NPIX) ? lq[i] * LOG2E : -1e30f;
    }
    const float* B = (z == 0) ? qb : (z == 1) ? kb : vb;
    float* Y       = (z == 0) ? g_Q : (z == 1) ? g_K : g_V;
    gemm_core(g_Xh2, g_Xl2, g_Wh2 + z * CIN * NCP, g_Wl2 + z * CIN * NCP, B, Y);
}

__global__ __launch_bounds__(128)
void gemm_proj(const float* __restrict__ B, float* __restrict__ Y)
{
    gemm_core(g_Oh2, g_Ol2, g_Wh2 + 3 * CIN * NCP, g_Wl2 + 3 * CIN * NCP, B, Y);
}

// ============================================================================
// Flash attention, fp16 m16n8k16, fixed-shift base-2 softmax, SPLIT-K over
// keys: blockIdx.z in {0,1} handles tiles [z*33, min(65, z*33+33)).
// Fixed shift => partials are plain sums: o_full = sum(o_z), l_full = sum(l_z).
// Writes unnormalized o (fp32, [h][q][d]) + partial l; attn_reduce combines.
//   Grid 17 x 8 x 2 = 272 blocks of 512 thr -> 2 CTAs/SM (32 warps/SM).
// ============================================================================
#define KS2 72
#define VS2 36

__global__ __launch_bounds__(512, 2)
void attn_kernel()
{
    __shared__ uint sK2[2][16 * KS2];
    __shared__ uint sV [2][32 * VS2];

    const int tid  = threadIdx.x;
    const int lane = tid & 31;
    const int w    = tid >> 5;
    const int g    = lane >> 2;
    const int tig  = lane & 3;
    const int h    = blockIdx.y;
    const int qb   = blockIdx.x;
    const int z    = blockIdx.z;

    const int t0    = z * TSPL;
    const int t_end = (t0 + TSPL < NTK) ? (t0 + TSPL) : NTK;

    const int q_row0 = qb * 256 + w * 16 + g;
    const int q_row1 = q_row0 + 8;

    const int fdp = tid >> 4;
    const int fkc = tid & 15;

    // ---- Q fragments, fp16 (scale includes log2 e) ----
    const float scale = 0.17677669529663687f * LOG2E;
    const int r0 = (q_row0 < NPIX) ? q_row0 : (NPIX - 1);
    const int r1 = (q_row1 < NPIX) ? q_row1 : (NPIX - 1);
    uint qa[2][4];
    #pragma unroll
    for (int kc = 0; kc < 2; kc++) {
        int d0 = kc * 16 + 2 * tig;
        const float* Qh = g_Q + (size_t)h * DHEAD * NPIX;
        qa[kc][0] = packh2(Qh[(d0)     * NPIX + r0] * scale, Qh[(d0 + 1) * NPIX + r0] * scale);
        qa[kc][1] = packh2(Qh[(d0)     * NPIX + r1] * scale, Qh[(d0 + 1) * NPIX + r1] * scale);
        qa[kc][2] = packh2(Qh[(d0 + 8) * NPIX + r0] * scale, Qh[(d0 + 9) * NPIX + r0] * scale);
        qa[kc][3] = packh2(Qh[(d0 + 8) * NPIX + r1] * scale, Qh[(d0 + 9) * NPIX + r1] * scale);
    }

    float o[4][4];
    #pragma unroll
    for (int db = 0; db < 4; db++)
        #pragma unroll
        for (int j = 0; j < 4; j++) o[db][j] = 0.f;

    float l0 = 0.f, l1 = 0.f;
    float4 rka, rkb, rva;

    const float* Kbase = g_K + (size_t)h * DHEAD * NPIX;
    const float* Vbase = g_V + (size_t)h * DHEAD * NPIX;

    // ---------- prologue: load + store first tile of this split ----------
    {
        int key0 = t0 * 64 + fkc * 4;   // always < NPIX (t0*64 <= 2112)
        if (tid < 256) {
            rka = *(const float4*)&Kbase[(2 * fdp)     * NPIX + key0];
            rkb = *(const float4*)&Kbase[(2 * fdp + 1) * NPIX + key0];
            uint4 kk;
            kk.x = packh2(rka.x, rkb.x);
            kk.y = packh2(rka.y, rkb.y);
            kk.z = packh2(rka.z, rkb.z);
            kk.w = packh2(rka.w, rkb.w);
            *(uint4*)&sK2[0][fdp * KS2 + fkc * 4] = kk;
        }
        rva = *(const float4*)&Vbase[fdp * NPIX + key0];
        uint2 vv;
        vv.x = packh2(rva.x, rva.y);
        vv.y = packh2(rva.z, rva.w);
        *(uint2*)&sV[0][fdp * VS2 + fkc * 2] = vv;
    }
    __syncthreads();

    for (int t = t0; t < t_end; t++) {
        const int cur = (t - t0) & 1;
        const int nxt = cur ^ 1;
        const bool more = (t + 1 < t_end);

        if (more) {
            int key0 = (t + 1) * 64 + fkc * 4;
            bool ok = (key0 < NPIX);
            int keyc = ok ? key0 : 0;
            if (tid < 256) {
                float4 ka = *(const float4*)&Kbase[(2 * fdp)     * NPIX + keyc];
                float4 kb = *(const float4*)&Kbase[(2 * fdp + 1) * NPIX + keyc];
                rka = ok ? ka : make_float4(0.f, 0.f, 0.f, 0.f);
                rkb = ok ? kb : make_float4(0.f, 0.f, 0.f, 0.f);
            }
            float4 va = *(const float4*)&Vbase[fdp * NPIX + keyc];
            rva = ok ? va : make_float4(0.f, 0.f, 0.f, 0.f);
        }

        // ---- S = Q K^T ----
        float c[8][4];
        #pragma unroll
        for (int nb = 0; nb < 8; nb++) {
            c[nb][0] = c[nb][1] = c[nb][2] = c[nb][3] = 0.f;
            #pragma unroll
            for (int kc = 0; kc < 2; kc++) {
                uint b0 = sK2[cur][(8 * kc + tig)     * KS2 + nb * 8 + g];
                uint b1 = sK2[cur][(8 * kc + tig + 4) * KS2 + nb * 8 + g];
                mma_f16(c[nb], qa[kc][0], qa[kc][1], qa[kc][2], qa[kc][3], b0, b1);
            }
        }

        // ---- fused bias + exp2 + pack + PV ----
        #pragma unroll
        for (int kc = 0; kc < 4; kc++) {
            const int nb0 = 2 * kc, nb1 = 2 * kc + 1;
            float2 lb0 = *(const float2*)&g_Lq[t * 64 + nb0 * 8 + 2 * tig];
            float2 lb1 = *(const float2*)&g_Lq[t * 64 + nb1 * 8 + 2 * tig];
            float p00 = ex2(c[nb0][0] + lb0.x);
            float p01 = ex2(c[nb0][1] + lb0.y);
            float p02 = ex2(c[nb0][2] + lb0.x);
            float p03 = ex2(c[nb0][3] + lb0.y);
            float p10 = ex2(c[nb1][0] + lb1.x);
            float p11 = ex2(c[nb1][1] + lb1.y);
            float p12 = ex2(c[nb1][2] + lb1.x);
            float p13 = ex2(c[nb1][3] + lb1.y);
            l0 += (p00 + p01) + (p10 + p11);
            l1 += (p02 + p03) + (p12 + p13);
            uint pa0 = packh2(p00, p01);
            uint pa1 = packh2(p02, p03);
            uint pa2 = packh2(p10, p11);
            uint pa3 = packh2(p12, p13);
            const int kp0 = 8 * kc + tig;
            #pragma unroll
            for (int db = 0; db < 4; db++) {
                uint b0 = sV[cur][(db * 8 + g) * VS2 + kp0];
                uint b1 = sV[cur][(db * 8 + g) * VS2 + kp0 + 4];
                mma_f16(o[db], pa0, pa1, pa2, pa3, b0, b1);
            }
        }

        if (more) {
            if (tid < 256) {
                uint4 kk;
                kk.x = packh2(rka.x, rkb.x);
                kk.y = packh2(rka.y, rkb.y);
                kk.z = packh2(rka.z, rkb.z);
                kk.w = packh2(rka.w, rkb.w);
                *(uint4*)&sK2[nxt][fdp * KS2 + fkc * 4] = kk;
            }
            uint2 vv;
            vv.x = packh2(rva.x, rva.y);
            vv.y = packh2(rva.z, rva.w);
            *(uint2*)&sV[nxt][fdp * VS2 + fkc * 2] = vv;
        }
        __syncthreads();
    }

    // ---- partial epilogue: quad-reduce l, write unnormalized partials ----
    l0 += __shfl_xor_sync(0xffffffffu, l0, 1);
    l0 += __shfl_xor_sync(0xffffffffu, l0, 2);
    l1 += __shfl_xor_sync(0xffffffffu, l1, 1);
    l1 += __shfl_xor_sync(0xffffffffu, l1, 2);
    if (tig == 0) {
        if (q_row0 < NPIX) g_Pl[z][h * NPIX + q_row0] = l0;
        if (q_row1 < NPIX) g_Pl[z][h * NPIX + q_row1] = l1;
    }
    #pragma unroll
    for (int db = 0; db < 4; db++) {
        int d = db * 8 + 2 * tig;
        if (q_row0 < NPIX)
            *(float2*)&g_Po[z][((size_t)h * NPIX + q_row0) * DHEAD + d] =
                make_float2(o[db][0], o[db][1]);
        if (q_row1 < NPIX)
            *(float2*)&g_Po[z][((size_t)h * NPIX + q_row1) * DHEAD + d] =
                make_float2(o[db][2], o[db][3]);
    }
}

// ============================================================================
// Combine split-K partials: O = (o0 + o1) / (l0 + l1), emit fp16-split pairs.
// ============================================================================
__global__ __launch_bounds__(256)
void attn_reduce()
{
    int idx = blockIdx.x * 256 + threadIdx.x;   // over NCP * NPIX
    if (idx >= NCP * NPIX) return;
    int cp = idx / NPIX;
    int n  = idx - cp * NPIX;
    int h  = cp >> 4;
    int dp = cp & 15;
    size_t ob = ((size_t)h * NPIX + n) * DHEAD + 2 * dp;
    float2 a0 = *(const float2*)&g_Po[0][ob];
    float2 a1 = *(const float2*)&g_Po[1][ob];
    float l = g_Pl[0][h * NPIX + n] + g_Pl[1][h * NPIX + n];
    float inv = 1.f / l;
    uint hi, lo;
    split_pair((a0.x + a1.x) * inv, (a0.y + a1.y) * inv, hi, lo);
    g_Oh2[idx] = hi;
    g_Ol2[idx] = lo;
}

// ============================================================================
extern "C" void kernel_launch(void* const* d_in, const int* in_sizes, int n_in,
                              void* d_out, int out_size)
{
    const float* query = (const float*)d_in[0];
    const float* q_w   = (const float*)d_in[1];
    const float* q_b   = (const float*)d_in[2];
    const float* k_w   = (const float*)d_in[3];
    const float* k_b   = (const float*)d_in[4];
    const float* v_w   = (const float*)d_in[5];
    const float* v_b   = (const float*)d_in[6];
    const float* p_w   = (const float*)d_in[7];
    const float* p_b   = (const float*)d_in[8];
    const float* lqw   = (const float*)d_in[9];
    float* out = (float*)d_out;

    split_w<<<(NWP_TOT + 255) / 256, 256>>>(q_w, k_w, v_w, p_w);

    dim3 gx((NPIX + 255) / 256, NCP, 1);
    split_x<<<gx, 256>>>(query);

    dim3 gq((NPIX + 63) / 64, 4, 3);                       // 65 x 4 x 3 = 780
    gemm_qkv<<<gq, 128>>>(q_b, k_b, v_b, lqw);

    dim3 ga((NPIX + 255) / 256, HEADS, NSPLIT);            // 17 x 8 x 2 = 272
    attn_kernel<<<ga, 512>>>();                            // -> g_Po/g_Pl

    attn_reduce<<<(NCP * NPIX + 255) / 256, 256>>>();      // -> g_Oh2/g_Ol2

    dim3 gp((NPIX + 63) / 64, 4, 1);                       // 65 x 4 = 260
    gemm_proj<<<gp, 128>>>(p_b, out);
}

// round 14
// speedup vs baseline: 1.6614x; 1.0810x over previous
#include <cuda_runtime.h>
#include <cuda_fp16.h>
#include <math.h>

#define NPIX 4140      // 46*90
#define CIN  256
#define HEADS 8
#define DHEAD 32
#define NTK  65        // key tiles of 64 (65*64 = 4160)
#define NSPLIT 2
#define TSPL 33        // tiles per split
#define LOG2E 1.4426950408889634f
#define NCP  (CIN / 2)              // 128 c-pairs

typedef unsigned int uint;

// ---------------- scratch (no allocations allowed) ----------------
__device__ float g_Q[CIN * NPIX];
__device__ float g_K[CIN * NPIX];
__device__ float g_V[CIN * NPIX];
__device__ float g_Po[NSPLIT][HEADS * NPIX * DHEAD];  // unnormalized o partials [h][q][d]
__device__ float g_Pl[NSPLIT][HEADS * NPIX];          // partial l
__device__ uint  g_Oh2[NCP * NPIX];     // attn out, fp16 hi pairs [cp][n]
__device__ uint  g_Ol2[NCP * NPIX];     // attn out, fp16 lo pairs
__device__ uint  g_Xh2[NCP * NPIX];     // query,  fp16 hi pairs [cp][n]
__device__ uint  g_Xl2[NCP * NPIX];     // query,  fp16 lo pairs
__device__ uint  g_Wh2[4 * CIN * NCP];  // q,k,v,p weights hi pairs [k][cp]
__device__ uint  g_Wl2[4 * CIN * NCP];  // weights lo pairs
__device__ float g_Lq[NTK * 64];        // log-quad bias * log2(e), padded

// ---------------- helpers ----------------
__device__ __forceinline__ float ex2(float x) {
    float y;
    asm("ex2.approx.f32 %0, %1;" : "=f"(y) : "f"(x));
    return y;
}

__device__ __forceinline__ uint packh2(float a, float b) {
    uint r;
    asm("cvt.rn.f16x2.f32 %0, %2, %1;" : "=r"(r) : "f"(a), "f"(b));
    return r;
}

__device__ __forceinline__ float2 unpackh2(uint u) {
    __half2 h = *reinterpret_cast<__half2*>(&u);
    return make_float2(__low2float(h), __high2float(h));
}

__device__ __forceinline__ void split_pair(float a, float b, uint& hi, uint& lo) {
    hi = packh2(a, b);
    float2 hv = unpackh2(hi);
    lo = packh2(a - hv.x, b - hv.y);
}

__device__ __forceinline__ void mma_f16(float c[4],
                                        uint a0, uint a1, uint a2, uint a3,
                                        uint b0, uint b1) {
    asm volatile(
        "mma.sync.aligned.m16n8k16.row.col.f32.f16.f16.f32 "
        "{%0,%1,%2,%3}, {%4,%5,%6,%7}, {%8,%9}, {%0,%1,%2,%3};"
        : "+f"(c[0]), "+f"(c[1]), "+f"(c[2]), "+f"(c[3])
        : "r"(a0), "r"(a1), "r"(a2), "r"(a3), "r"(b0), "r"(b1));
}

__device__ __forceinline__ void ldsm_x4(uint& r0, uint& r1, uint& r2, uint& r3,
                                        uint addr) {
    asm volatile("ldmatrix.sync.aligned.m8n8.x4.shared.b16 {%0,%1,%2,%3}, [%4];"
                 : "=r"(r0), "=r"(r1), "=r"(r2), "=r"(r3) : "r"(addr));
}
__device__ __forceinline__ void ldsm_x4_t(uint& r0, uint& r1, uint& r2, uint& r3,
                                          uint addr) {
    asm volatile("ldmatrix.sync.aligned.m8n8.x4.trans.shared.b16 {%0,%1,%2,%3}, [%4];"
                 : "=r"(r0), "=r"(r1), "=r"(r2), "=r"(r3) : "r"(addr));
}

__device__ __forceinline__ void cp_async16(void* dst, const void* src, int src_sz) {
    uint d = (uint)__cvta_generic_to_shared(dst);
    asm volatile("cp.async.cg.shared.global [%0], [%1], 16, %2;"
                 :: "r"(d), "l"(src), "r"(src_sz));
}
__device__ __forceinline__ void cp_commit() { asm volatile("cp.async.commit_group;"); }
__device__ __forceinline__ void cp_wait0()  { asm volatile("cp.async.wait_group 0;"); }

// ============================================================================
// Pre-split weights AND query -> fp16 (hi,lo) c-pairs (single launch)
// ============================================================================
#define NWP_TOT (4 * CIN * NCP)        // 131072 pair entries
#define NXP_TOT (NCP * NPIX)           // 529920 pair entries

__global__ __launch_bounds__(256)
void split_wx(const float* __restrict__ qw, const float* __restrict__ kw,
              const float* __restrict__ vw, const float* __restrict__ pw,
              const float* __restrict__ query)
{
    int i = blockIdx.x * 256 + threadIdx.x;
    if (i < NWP_TOT) {
        int m   = i >> 15;
        int rem = i & 32767;
        int k   = rem >> 7;
        int cp  = rem & 127;
        const float* W = (m == 0) ? qw : (m == 1) ? kw : (m == 2) ? vw : pw;
        uint hi, lo;
        split_pair(W[k * CIN + 2 * cp], W[k * CIN + 2 * cp + 1], hi, lo);
        g_Wh2[i] = hi;
        g_Wl2[i] = lo;
    } else {
        int j = i - NWP_TOT;
        if (j < NXP_TOT) {
            int cp = j / NPIX;
            int n  = j - cp * NPIX;
            uint hi, lo;
            split_pair(query[(2 * cp) * NPIX + n], query[(2 * cp + 1) * NPIX + n], hi, lo);
            g_Xh2[j] = hi;
            g_Xl2[j] = lo;
        }
    }
}

// ============================================================================
// 3-term fp16-split GEMM (hh + hl + lh), m16n8k16, pre-split operands.
// Tile 64k x 64n, 128 thr / 4 warps. k-step 32 (16 c-pairs), double-buffered.
// ============================================================================
#define WST 20
#define XST 72

__device__ __forceinline__
void gemm_core(const uint* __restrict__ Xh2, const uint* __restrict__ Xl2,
               const uint* __restrict__ Wh2, const uint* __restrict__ Wl2,
               const float* __restrict__ bias, float* __restrict__ Y)
{
    __shared__ uint sWh[2][64 * WST], sWl[2][64 * WST];
    __shared__ uint sXh[2][16 * XST], sXl[2][16 * XST];

    const int tid  = threadIdx.x;
    const int w    = tid >> 5;
    const int lane = tid & 31;
    const int g    = lane >> 2;
    const int tig  = lane & 3;
    const int k0   = blockIdx.y * 64;
    const int n0   = blockIdx.x * 64;

    {
        #pragma unroll
        for (int r = 0; r < 2; r++) {
            int idx = tid + 128 * r;
            int wk = idx >> 2, wcp = (idx & 3) * 4;
            cp_async16(&sWh[0][wk * WST + wcp], &Wh2[(k0 + wk) * NCP + wcp], 16);
            cp_async16(&sWl[0][wk * WST + wcp], &Wl2[(k0 + wk) * NCP + wcp], 16);
        }
        #pragma unroll
        for (int r = 0; r < 2; r++) {
            int idx = tid + 128 * r;
            int xcp = idx >> 4, xn = (idx & 15) * 4;
            int n = n0 + xn;
            int ok = (n < NPIX);
            cp_async16(&sXh[0][xcp * XST + xn], &Xh2[xcp * NPIX + (ok ? n : 0)], ok ? 16 : 0);
            cp_async16(&sXl[0][xcp * XST + xn], &Xl2[xcp * NPIX + (ok ? n : 0)], ok ? 16 : 0);
        }
        cp_commit();
    }

    float acc[8][4];
    #pragma unroll
    for (int nb = 0; nb < 8; nb++)
        #pragma unroll
        for (int i = 0; i < 4; i++) acc[nb][i] = 0.f;

    cp_wait0();
    __syncthreads();

    #pragma unroll
    for (int it = 0; it < 8; it++) {
        const int cur = it & 1;
        const int nxt = cur ^ 1;
        const bool more = (it + 1 < 8);

        if (more) {
            const int cc2 = (it + 1) * 16;
            #pragma unroll
            for (int r = 0; r < 2; r++) {
                int idx = tid + 128 * r;
                int wk = idx >> 2, wcp = (idx & 3) * 4;
                cp_async16(&sWh[nxt][wk * WST + wcp],
                           &Wh2[(k0 + wk) * NCP + cc2 + wcp], 16);
                cp_async16(&sWl[nxt][wk * WST + wcp],
                           &Wl2[(k0 + wk) * NCP + cc2 + wcp], 16);
            }
            #pragma unroll
            for (int r = 0; r < 2; r++) {
                int idx = tid + 128 * r;
                int xcp = idx >> 4, xn = (idx & 15) * 4;
                int n = n0 + xn;
                int ok = (n < NPIX);
                cp_async16(&sXh[nxt][xcp * XST + xn],
                           &Xh2[(cc2 + xcp) * NPIX + (ok ? n : 0)], ok ? 16 : 0);
                cp_async16(&sXl[nxt][xcp * XST + xn],
                           &Xl2[(cc2 + xcp) * NPIX + (ok ? n : 0)], ok ? 16 : 0);
            }
            cp_commit();
        }

        #pragma unroll
        for (int kb = 0; kb < 2; kb++) {
            const int ar = (w * 16 + g) * WST + kb * 8 + tig;
            uint ah0 = sWh[cur][ar];
            uint ah1 = sWh[cur][ar + 8 * WST];
            uint ah2 = sWh[cur][ar + 4];
            uint ah3 = sWh[cur][ar + 8 * WST + 4];
            uint al0 = sWl[cur][ar];
            uint al1 = sWl[cur][ar + 8 * WST];
            uint al2 = sWl[cur][ar + 4];
            uint al3 = sWl[cur][ar + 8 * WST + 4];
            const int br0 = (kb * 8 + tig) * XST + g;
            const int br1 = br0 + 4 * XST;
            #pragma unroll
            for (int nb = 0; nb < 8; nb++) {
                uint bh0 = sXh[cur][br0 + nb * 8];
                uint bh1 = sXh[cur][br1 + nb * 8];
                uint bl0 = sXl[cur][br0 + nb * 8];
                uint bl1 = sXl[cur][br1 + nb * 8];
                mma_f16(acc[nb], ah0, ah1, ah2, ah3, bh0, bh1);
                mma_f16(acc[nb], ah0, ah1, ah2, ah3, bl0, bl1);
                mma_f16(acc[nb], al0, al1, al2, al3, bh0, bh1);
            }
        }

        if (more) cp_wait0();
        __syncthreads();
    }

    const int r0 = k0 + w * 16 + g;
    const int r1 = r0 + 8;
    const float bv0 = __ldg(&bias[r0]);
    const float bv1 = __ldg(&bias[r1]);
    #pragma unroll
    for (int nb = 0; nb < 8; nb++) {
        int n = n0 + nb * 8 + 2 * tig;
        if (n < NPIX) {
            float2 y0 = make_float2(acc[nb][0] + bv0, acc[nb][1] + bv0);
            float2 y1 = make_float2(acc[nb][2] + bv1, acc[nb][3] + bv1);
            *(float2*)&Y[r0 * NPIX + n] = y0;
            *(float2*)&Y[r1 * NPIX + n] = y1;
        }
    }
}

__global__ __launch_bounds__(128)
void gemm_qkv(const float* __restrict__ qb, const float* __restrict__ kb,
              const float* __restrict__ vb, const float* __restrict__ lq)
{
    int z = blockIdx.z;
    if (z == 0 && blockIdx.x == 0 && blockIdx.y == 0) {
        for (int i = threadIdx.x; i < NTK * 64; i += 128)
            g_Lq[i] = (i < NPIX) ? lq[i] * LOG2E : -1e30f;
    }
    const float* B = (z == 0) ? qb : (z == 1) ? kb : vb;
    float* Y       = (z == 0) ? g_Q : (z == 1) ? g_K : g_V;
    gemm_core(g_Xh2, g_Xl2, g_Wh2 + z * CIN * NCP, g_Wl2 + z * CIN * NCP, B, Y);
}

__global__ __launch_bounds__(128)
void gemm_proj(const float* __restrict__ B, float* __restrict__ Y)
{
    gemm_core(g_Oh2, g_Ol2, g_Wh2 + 3 * CIN * NCP, g_Wl2 + 3 * CIN * NCP, B, Y);
}

// ============================================================================
// Flash attention, fp16 m16n8k16, fixed-shift base-2 softmax, split-K (z=0,1),
// K/V fragments via ldmatrix (16 LDSM replaces 64 scalar LDS per tile).
//   sK: f16 [d][key] rows, 72-f16 stride (36 words) -> ldmatrix.x4.trans,
//       one op per nb gives (b0,b1) for both kc chunks (lane = d row).
//   sV: half2 [d][key-pair] rows, 36-word stride -> ldmatrix.x4 (non-trans),
//       one op per (kc, db-pair).
//   Grid 17 x 8 x 2 = 272 blocks of 512 thr -> 2 CTAs/SM (32 warps/SM).
// ============================================================================
#define KSW 36     // words per K d-row (64 keys f16 = 32 words + 4 pad)
#define VSW 36     // words per V d-row (32 key-pair words + 4 pad)

__global__ __launch_bounds__(512, 2)
void attn_kernel()
{
    __shared__ uint sK[2][32 * KSW];
    __shared__ uint sV[2][32 * VSW];

    const int tid  = threadIdx.x;
    const int lane = tid & 31;
    const int w    = tid >> 5;
    const int g    = lane >> 2;
    const int tig  = lane & 3;
    const int h    = blockIdx.y;
    const int qb   = blockIdx.x;
    const int z    = blockIdx.z;

    const int t0    = z * TSPL;
    const int t_end = (t0 + TSPL < NTK) ? (t0 + TSPL) : NTK;

    const int q_row0 = qb * 256 + w * 16 + g;
    const int q_row1 = q_row0 + 8;

    // fill roles: all 512 threads; fd = d (0..31), fkc = key chunk of 4
    const int fd  = tid >> 4;
    const int fkc = tid & 15;

    // smem u32 bases for ldmatrix
    const uint skb0 = (uint)__cvta_generic_to_shared(&sK[0][0]);
    const uint skb1 = (uint)__cvta_generic_to_shared(&sK[1][0]);
    const uint svb0 = (uint)__cvta_generic_to_shared(&sV[0][0]);
    const uint svb1 = (uint)__cvta_generic_to_shared(&sV[1][0]);

    // ldmatrix lane->address offsets (in words)
    // K (trans): lane = d row; per nb: addr = d*KSW + nb*4
    const uint koff = (uint)lane * KSW;
    // V (non-trans): matrix m = lane/8; d = dbp*16 + (lane>>4)*8 + (lane&7),
    // word col = kc*8 + ((lane>>3)&1)*4
    const uint vrow = ((lane >> 4) * 8 + (lane & 7)) * VSW + ((lane >> 3) & 1) * 4;

    // ---- Q fragments, fp16 (scale includes log2 e) ----
    const float scale = 0.17677669529663687f * LOG2E;
    const int r0 = (q_row0 < NPIX) ? q_row0 : (NPIX - 1);
    const int r1 = (q_row1 < NPIX) ? q_row1 : (NPIX - 1);
    uint qa[2][4];
    #pragma unroll
    for (int kc = 0; kc < 2; kc++) {
        int d0 = kc * 16 + 2 * tig;
        const float* Qh = g_Q + (size_t)h * DHEAD * NPIX;
        qa[kc][0] = packh2(Qh[(d0)     * NPIX + r0] * scale, Qh[(d0 + 1) * NPIX + r0] * scale);
        qa[kc][1] = packh2(Qh[(d0)     * NPIX + r1] * scale, Qh[(d0 + 1) * NPIX + r1] * scale);
        qa[kc][2] = packh2(Qh[(d0 + 8) * NPIX + r0] * scale, Qh[(d0 + 9) * NPIX + r0] * scale);
        qa[kc][3] = packh2(Qh[(d0 + 8) * NPIX + r1] * scale, Qh[(d0 + 9) * NPIX + r1] * scale);
    }

    float o[4][4];
    #pragma unroll
    for (int db = 0; db < 4; db++)
        #pragma unroll
        for (int j = 0; j < 4; j++) o[db][j] = 0.f;

    float l0 = 0.f, l1 = 0.f;
    float4 rk, rv;

    const float* Kbase = g_K + (size_t)h * DHEAD * NPIX;
    const float* Vbase = g_V + (size_t)h * DHEAD * NPIX;

    // ---------- prologue: load + store first tile of this split ----------
    {
        int key0 = t0 * 64 + fkc * 4;   // always valid (t0*64 + 63 < NPIX)
        rk = *(const float4*)&Kbase[fd * NPIX + key0];
        rv = *(const float4*)&Vbase[fd * NPIX + key0];
        uint2 kk = make_uint2(packh2(rk.x, rk.y), packh2(rk.z, rk.w));
        uint2 vv = make_uint2(packh2(rv.x, rv.y), packh2(rv.z, rv.w));
        *(uint2*)&sK[0][fd * KSW + fkc * 2] = kk;
        *(uint2*)&sV[0][fd * VSW + fkc * 2] = vv;
    }
    __syncthreads();

    for (int t = t0; t < t_end; t++) {
        const int cur = (t - t0) & 1;
        const bool more = (t + 1 < t_end);
        const uint skc = cur ? skb1 : skb0;
        const uint svc = cur ? svb1 : svb0;

        // ---- issue next-tile global loads into registers ----
        if (more) {
            int key0 = (t + 1) * 64 + fkc * 4;
            bool ok = (key0 < NPIX);
            int keyc = ok ? key0 : 0;
            float4 ka = *(const float4*)&Kbase[fd * NPIX + keyc];
            float4 va = *(const float4*)&Vbase[fd * NPIX + keyc];
            rk = ok ? ka : make_float4(0.f, 0.f, 0.f, 0.f);
            rv = ok ? va : make_float4(0.f, 0.f, 0.f, 0.f);
        }

        // ---- S = Q K^T : per nb one ldmatrix.x4.trans gives all 4 B-regs ----
        float c[8][4];
        #pragma unroll
        for (int nb = 0; nb < 8; nb++) {
            c[nb][0] = c[nb][1] = c[nb][2] = c[nb][3] = 0.f;
            uint b00, b01, b10, b11;
            ldsm_x4_t(b00, b01, b10, b11, skc + (koff + nb * 4) * 4);
            mma_f16(c[nb], qa[0][0], qa[0][1], qa[0][2], qa[0][3], b00, b01);
            mma_f16(c[nb], qa[1][0], qa[1][1], qa[1][2], qa[1][3], b10, b11);
        }

        // ---- fused bias + exp2 + pack + PV (ldmatrix V) ----
        #pragma unroll
        for (int kc = 0; kc < 4; kc++) {
            const int nb0 = 2 * kc, nb1 = 2 * kc + 1;
            float2 lb0 = *(const float2*)&g_Lq[t * 64 + nb0 * 8 + 2 * tig];
            float2 lb1 = *(const float2*)&g_Lq[t * 64 + nb1 * 8 + 2 * tig];
            float p00 = ex2(c[nb0][0] + lb0.x);
            float p01 = ex2(c[nb0][1] + lb0.y);
            float p02 = ex2(c[nb0][2] + lb0.x);
            float p03 = ex2(c[nb0][3] + lb0.y);
            float p10 = ex2(c[nb1][0] + lb1.x);
            float p11 = ex2(c[nb1][1] + lb1.y);
            float p12 = ex2(c[nb1][2] + lb1.x);
            float p13 = ex2(c[nb1][3] + lb1.y);
            l0 += (p00 + p01) + (p10 + p11);
            l1 += (p02 + p03) + (p12 + p13);
            uint pa0 = packh2(p00, p01);
            uint pa1 = packh2(p02, p03);
            uint pa2 = packh2(p10, p11);
            uint pa3 = packh2(p12, p13);
            #pragma unroll
            for (int dbp = 0; dbp < 2; dbp++) {
                uint v00, v01, v10, v11;
                uint addr = svc + (vrow + dbp * 16 * VSW + kc * 8) * 4;
                ldsm_x4(v00, v01, v10, v11, addr);
                mma_f16(o[2 * dbp],     pa0, pa1, pa2, pa3, v00, v01);
                mma_f16(o[2 * dbp + 1], pa0, pa1, pa2, pa3, v10, v11);
            }
        }

        // ---- store next tile into the other buffer ----
        if (more) {
            const int nxt = cur ^ 1;
            uint2 kk = make_uint2(packh2(rk.x, rk.y), packh2(rk.z, rk.w));
            uint2 vv = make_uint2(packh2(rv.x, rv.y), packh2(rv.z, rv.w));
            *(uint2*)&sK[nxt][fd * KSW + fkc * 2] = kk;
            *(uint2*)&sV[nxt][fd * VSW + fkc * 2] = vv;
        }
        __syncthreads();
    }

    // ---- partial epilogue: quad-reduce l, write unnormalized partials ----
    l0 += __shfl_xor_sync(0xffffffffu, l0, 1);
    l0 += __shfl_xor_sync(0xffffffffu, l0, 2);
    l1 += __shfl_xor_sync(0xffffffffu, l1, 1);
    l1 += __shfl_xor_sync(0xffffffffu, l1, 2);
    if (tig == 0) {
        if (q_row0 < NPIX) g_Pl[z][h * NPIX + q_row0] = l0;
        if (q_row1 < NPIX) g_Pl[z][h * NPIX + q_row1] = l1;
    }
    #pragma unroll
    for (int db = 0; db < 4; db++) {
        int d = db * 8 + 2 * tig;
        if (q_row0 < NPIX)
            *(float2*)&g_Po[z][((size_t)h * NPIX + q_row0) * DHEAD + d] =
                make_float2(o[db][0], o[db][1]);
        if (q_row1 < NPIX)
            *(float2*)&g_Po[z][((size_t)h * NPIX + q_row1) * DHEAD + d] =
                make_float2(o[db][2], o[db][3]);
    }
}

// ============================================================================
// Combine split-K partials: O = (o0 + o1) / (l0 + l1), emit fp16-split pairs.
// ============================================================================
__global__ __launch_bounds__(256)
void attn_reduce()
{
    int idx = blockIdx.x * 256 + threadIdx.x;   // over NCP * NPIX
    if (idx >= NCP * NPIX) return;
    int cp = idx / NPIX;
    int n  = idx - cp * NPIX;
    int h  = cp >> 4;
    int dp = cp & 15;
    size_t ob = ((size_t)h * NPIX + n) * DHEAD + 2 * dp;
    float2 a0 = *(const float2*)&g_Po[0][ob];
    float2 a1 = *(const float2*)&g_Po[1][ob];
    float l = g_Pl[0][h * NPIX + n] + g_Pl[1][h * NPIX + n];
    float inv = 1.f / l;
    uint hi, lo;
    split_pair((a0.x + a1.x) * inv, (a0.y + a1.y) * inv, hi, lo);
    g_Oh2[idx] = hi;
    g_Ol2[idx] = lo;
}

// ============================================================================
extern "C" void kernel_launch(void* const* d_in, const int* in_sizes, int n_in,
                              void* d_out, int out_size)
{
    const float* query = (const float*)d_in[0];
    const float* q_w   = (const float*)d_in[1];
    const float* q_b   = (const float*)d_in[2];
    const float* k_w   = (const float*)d_in[3];
    const float* k_b   = (const float*)d_in[4];
    const float* v_w   = (const float*)d_in[5];
    const float* v_b   = (const float*)d_in[6];
    const float* p_w   = (const float*)d_in[7];
    const float* p_b   = (const float*)d_in[8];
    const float* lqw   = (const float*)d_in[9];
    float* out = (float*)d_out;

    split_wx<<<(NWP_TOT + NXP_TOT + 255) / 256, 256>>>(q_w, k_w, v_w, p_w, query);

    dim3 gq((NPIX + 63) / 64, 4, 3);                       // 65 x 4 x 3 = 780
    gemm_qkv<<<gq, 128>>>(q_b, k_b, v_b, lqw);

    dim3 ga((NPIX + 255) / 256, HEADS, NSPLIT);            // 17 x 8 x 2 = 272
    attn_kernel<<<ga, 512>>>();                            // -> g_Po/g_Pl

    attn_reduce<<<(NCP * NPIX + 255) / 256, 256>>>();      // -> g_Oh2/g_Ol2

    dim3 gp((NPIX + 63) / 64, 4, 1);                       // 65 x 4 = 260
    gemm_proj<<<gp, 128>>>(p_b, out);
}

// round 15
// speedup vs baseline: 1.6666x; 1.0031x over previous
#include <cuda_runtime.h>
#include <cuda_fp16.h>
#include <math.h>

#define NPIX 4140      // 46*90
#define CIN  256
#define HEADS 8
#define DHEAD 32
#define NTK  65        // key tiles of 64 (65*64 = 4160)
#define NSPLIT 2
#define TSPL 33        // tiles per split
#define LOG2E 1.4426950408889634f
#define NCP  (CIN / 2)              // 128 c-pairs

typedef unsigned int uint;

// ---------------- scratch (no allocations allowed) ----------------
__device__ float g_Q[CIN * NPIX];
__device__ float g_K[CIN * NPIX];
__device__ float g_V[CIN * NPIX];
__device__ float g_Po[NSPLIT][HEADS * NPIX * DHEAD];  // unnormalized o partials [h][q][d]
__device__ float g_Pl[NSPLIT][HEADS * NPIX];          // partial l
__device__ uint  g_Oh2[NCP * NPIX];     // attn out, fp16 hi pairs [cp][n]
__device__ uint  g_Ol2[NCP * NPIX];     // attn out, fp16 lo pairs
__device__ uint  g_Xh2[NCP * NPIX];     // query,  fp16 hi pairs [cp][n]
__device__ uint  g_Xl2[NCP * NPIX];     // query,  fp16 lo pairs
__device__ uint  g_Wh2[4 * CIN * NCP];  // q,k,v,p weights hi pairs [k][cp]
__device__ uint  g_Wl2[4 * CIN * NCP];  // weights lo pairs
__device__ float g_Lq[NTK * 64];        // log-quad bias * log2(e), padded

// ---------------- helpers ----------------
__device__ __forceinline__ float ex2(float x) {
    float y;
    asm("ex2.approx.f32 %0, %1;" : "=f"(y) : "f"(x));
    return y;
}

__device__ __forceinline__ uint packh2(float a, float b) {
    uint r;
    asm("cvt.rn.f16x2.f32 %0, %2, %1;" : "=r"(r) : "f"(a), "f"(b));
    return r;
}

__device__ __forceinline__ float2 unpackh2(uint u) {
    __half2 h = *reinterpret_cast<__half2*>(&u);
    return make_float2(__low2float(h), __high2float(h));
}

__device__ __forceinline__ void split_pair(float a, float b, uint& hi, uint& lo) {
    hi = packh2(a, b);
    float2 hv = unpackh2(hi);
    lo = packh2(a - hv.x, b - hv.y);
}

__device__ __forceinline__ void mma_f16(float c[4],
                                        uint a0, uint a1, uint a2, uint a3,
                                        uint b0, uint b1) {
    asm volatile(
        "mma.sync.aligned.m16n8k16.row.col.f32.f16.f16.f32 "
        "{%0,%1,%2,%3}, {%4,%5,%6,%7}, {%8,%9}, {%0,%1,%2,%3};"
        : "+f"(c[0]), "+f"(c[1]), "+f"(c[2]), "+f"(c[3])
        : "r"(a0), "r"(a1), "r"(a2), "r"(a3), "r"(b0), "r"(b1));
}

__device__ __forceinline__ void ldsm_x4(uint& r0, uint& r1, uint& r2, uint& r3,
                                        uint addr) {
    asm volatile("ldmatrix.sync.aligned.m8n8.x4.shared.b16 {%0,%1,%2,%3}, [%4];"
                 : "=r"(r0), "=r"(r1), "=r"(r2), "=r"(r3) : "r"(addr));
}
__device__ __forceinline__ void ldsm_x4_t(uint& r0, uint& r1, uint& r2, uint& r3,
                                          uint addr) {
    asm volatile("ldmatrix.sync.aligned.m8n8.x4.trans.shared.b16 {%0,%1,%2,%3}, [%4];"
                 : "=r"(r0), "=r"(r1), "=r"(r2), "=r"(r3) : "r"(addr));
}

__device__ __forceinline__ void cp_async16(void* dst, const void* src, int src_sz) {
    uint d = (uint)__cvta_generic_to_shared(dst);
    asm volatile("cp.async.cg.shared.global [%0], [%1], 16, %2;"
                 :: "r"(d), "l"(src), "r"(src_sz));
}
__device__ __forceinline__ void cp_commit() { asm volatile("cp.async.commit_group;"); }
__device__ __forceinline__ void cp_wait0()  { asm volatile("cp.async.wait_group 0;"); }

// ============================================================================
// Pre-split weights AND query -> fp16 (hi,lo) c-pairs (single launch)
// ============================================================================
#define NWP_TOT (4 * CIN * NCP)        // 131072 pair entries
#define NXP_TOT (NCP * NPIX)           // 529920 pair entries

__global__ __launch_bounds__(256)
void split_wx(const float* __restrict__ qw, const float* __restrict__ kw,
              const float* __restrict__ vw, const float* __restrict__ pw,
              const float* __restrict__ query)
{
    int i = blockIdx.x * 256 + threadIdx.x;
    if (i < NWP_TOT) {
        int m   = i >> 15;
        int rem = i & 32767;
        int k   = rem >> 7;
        int cp  = rem & 127;
        const float* W = (m == 0) ? qw : (m == 1) ? kw : (m == 2) ? vw : pw;
        uint hi, lo;
        split_pair(W[k * CIN + 2 * cp], W[k * CIN + 2 * cp + 1], hi, lo);
        g_Wh2[i] = hi;
        g_Wl2[i] = lo;
    } else {
        int j = i - NWP_TOT;
        if (j < NXP_TOT) {
            int cp = j / NPIX;
            int n  = j - cp * NPIX;
            uint hi, lo;
            split_pair(query[(2 * cp) * NPIX + n], query[(2 * cp + 1) * NPIX + n], hi, lo);
            g_Xh2[j] = hi;
            g_Xl2[j] = lo;
        }
    }
}

// ============================================================================
// 3-term fp16-split GEMM (hh + hl + lh), m16n8k16, pre-split operands.
// Tile 64k x 64n, 128 thr / 4 warps. k-step 32 (16 c-pairs), double-buffered.
// ============================================================================
#define WST 20
#define XST 72

__device__ __forceinline__
void gemm_core(const uint* __restrict__ Xh2, const uint* __restrict__ Xl2,
               const uint* __restrict__ Wh2, const uint* __restrict__ Wl2,
               const float* __restrict__ bias, float* __restrict__ Y)
{
    __shared__ uint sWh[2][64 * WST], sWl[2][64 * WST];
    __shared__ uint sXh[2][16 * XST], sXl[2][16 * XST];

    const int tid  = threadIdx.x;
    const int w    = tid >> 5;
    const int lane = tid & 31;
    const int g    = lane >> 2;
    const int tig  = lane & 3;
    const int k0   = blockIdx.y * 64;
    const int n0   = blockIdx.x * 64;

    {
        #pragma unroll
        for (int r = 0; r < 2; r++) {
            int idx = tid + 128 * r;
            int wk = idx >> 2, wcp = (idx & 3) * 4;
            cp_async16(&sWh[0][wk * WST + wcp], &Wh2[(k0 + wk) * NCP + wcp], 16);
            cp_async16(&sWl[0][wk * WST + wcp], &Wl2[(k0 + wk) * NCP + wcp], 16);
        }
        #pragma unroll
        for (int r = 0; r < 2; r++) {
            int idx = tid + 128 * r;
            int xcp = idx >> 4, xn = (idx & 15) * 4;
            int n = n0 + xn;
            int ok = (n < NPIX);
            cp_async16(&sXh[0][xcp * XST + xn], &Xh2[xcp * NPIX + (ok ? n : 0)], ok ? 16 : 0);
            cp_async16(&sXl[0][xcp * XST + xn], &Xl2[xcp * NPIX + (ok ? n : 0)], ok ? 16 : 0);
        }
        cp_commit();
    }

    float acc[8][4];
    #pragma unroll
    for (int nb = 0; nb < 8; nb++)
        #pragma unroll
        for (int i = 0; i < 4; i++) acc[nb][i] = 0.f;

    cp_wait0();
    __syncthreads();

    #pragma unroll
    for (int it = 0; it < 8; it++) {
        const int cur = it & 1;
        const int nxt = cur ^ 1;
        const bool more = (it + 1 < 8);

        if (more) {
            const int cc2 = (it + 1) * 16;
            #pragma unroll
            for (int r = 0; r < 2; r++) {
                int idx = tid + 128 * r;
                int wk = idx >> 2, wcp = (idx & 3) * 4;
                cp_async16(&sWh[nxt][wk * WST + wcp],
                           &Wh2[(k0 + wk) * NCP + cc2 + wcp], 16);
                cp_async16(&sWl[nxt][wk * WST + wcp],
                           &Wl2[(k0 + wk) * NCP + cc2 + wcp], 16);
            }
            #pragma unroll
            for (int r = 0; r < 2; r++) {
                int idx = tid + 128 * r;
                int xcp = idx >> 4, xn = (idx & 15) * 4;
                int n = n0 + xn;
                int ok = (n < NPIX);
                cp_async16(&sXh[nxt][xcp * XST + xn],
                           &Xh2[(cc2 + xcp) * NPIX + (ok ? n : 0)], ok ? 16 : 0);
                cp_async16(&sXl[nxt][xcp * XST + xn],
                           &Xl2[(cc2 + xcp) * NPIX + (ok ? n : 0)], ok ? 16 : 0);
            }
            cp_commit();
        }

        #pragma unroll
        for (int kb = 0; kb < 2; kb++) {
            const int ar = (w * 16 + g) * WST + kb * 8 + tig;
            uint ah0 = sWh[cur][ar];
            uint ah1 = sWh[cur][ar + 8 * WST];
            uint ah2 = sWh[cur][ar + 4];
            uint ah3 = sWh[cur][ar + 8 * WST + 4];
            uint al0 = sWl[cur][ar];
            uint al1 = sWl[cur][ar + 8 * WST];
            uint al2 = sWl[cur][ar + 4];
            uint al3 = sWl[cur][ar + 8 * WST + 4];
            const int br0 = (kb * 8 + tig) * XST + g;
            const int br1 = br0 + 4 * XST;
            #pragma unroll
            for (int nb = 0; nb < 8; nb++) {
                uint bh0 = sXh[cur][br0 + nb * 8];
                uint bh1 = sXh[cur][br1 + nb * 8];
                uint bl0 = sXl[cur][br0 + nb * 8];
                uint bl1 = sXl[cur][br1 + nb * 8];
                mma_f16(acc[nb], ah0, ah1, ah2, ah3, bh0, bh1);
                mma_f16(acc[nb], ah0, ah1, ah2, ah3, bl0, bl1);
                mma_f16(acc[nb], al0, al1, al2, al3, bh0, bh1);
            }
        }

        if (more) cp_wait0();
        __syncthreads();
    }

    const int r0 = k0 + w * 16 + g;
    const int r1 = r0 + 8;
    const float bv0 = __ldg(&bias[r0]);
    const float bv1 = __ldg(&bias[r1]);
    #pragma unroll
    for (int nb = 0; nb < 8; nb++) {
        int n = n0 + nb * 8 + 2 * tig;
        if (n < NPIX) {
            float2 y0 = make_float2(acc[nb][0] + bv0, acc[nb][1] + bv0);
            float2 y1 = make_float2(acc[nb][2] + bv1, acc[nb][3] + bv1);
            *(float2*)&Y[r0 * NPIX + n] = y0;
            *(float2*)&Y[r1 * NPIX + n] = y1;
        }
    }
}

__global__ __launch_bounds__(128)
void gemm_qkv(const float* __restrict__ qb, const float* __restrict__ kb,
              const float* __restrict__ vb, const float* __restrict__ lq)
{
    int z = blockIdx.z;
    if (z == 0 && blockIdx.x == 0 && blockIdx.y == 0) {
        for (int i = threadIdx.x; i < NTK * 64; i += 128)
            g_Lq[i] = (i < NPIX) ? lq[i] * LOG2E : -1e30f;
    }
    const float* B = (z == 0) ? qb : (z == 1) ? kb : vb;
    float* Y       = (z == 0) ? g_Q : (z == 1) ? g_K : g_V;
    gemm_core(g_Xh2, g_Xl2, g_Wh2 + z * CIN * NCP, g_Wl2 + z * CIN * NCP, B, Y);
}

__global__ __launch_bounds__(128)
void gemm_proj(const float* __restrict__ B, float* __restrict__ Y)
{
    gemm_core(g_Oh2, g_Ol2, g_Wh2 + 3 * CIN * NCP, g_Wl2 + 3 * CIN * NCP, B, Y);
}

// ============================================================================
// Flash attention, fp16 m16n8k16, fixed-shift base-2 softmax, split-K (z=0,1),
// K/V fragments via ldmatrix (16 LDSM replaces 64 scalar LDS per tile).
//   sK: f16 [d][key] rows, 72-f16 stride (36 words) -> ldmatrix.x4.trans,
//       one op per nb gives (b0,b1) for both kc chunks (lane = d row).
//   sV: half2 [d][key-pair] rows, 36-word stride -> ldmatrix.x4 (non-trans),
//       one op per (kc, db-pair).
//   Grid 17 x 8 x 2 = 272 blocks of 512 thr -> 2 CTAs/SM (32 warps/SM).
// ============================================================================
#define KSW 36     // words per K d-row (64 keys f16 = 32 words + 4 pad)
#define VSW 36     // words per V d-row (32 key-pair words + 4 pad)

__global__ __launch_bounds__(512, 2)
void attn_kernel()
{
    __shared__ uint sK[2][32 * KSW];
    __shared__ uint sV[2][32 * VSW];

    const int tid  = threadIdx.x;
    const int lane = tid & 31;
    const int w    = tid >> 5;
    const int g    = lane >> 2;
    const int tig  = lane & 3;
    const int h    = blockIdx.y;
    const int qb   = blockIdx.x;
    const int z    = blockIdx.z;

    const int t0    = z * TSPL;
    const int t_end = (t0 + TSPL < NTK) ? (t0 + TSPL) : NTK;

    const int q_row0 = qb * 256 + w * 16 + g;
    const int q_row1 = q_row0 + 8;

    // fill roles: all 512 threads; fd = d (0..31), fkc = key chunk of 4
    const int fd  = tid >> 4;
    const int fkc = tid & 15;

    // smem u32 bases for ldmatrix
    const uint skb0 = (uint)__cvta_generic_to_shared(&sK[0][0]);
    const uint skb1 = (uint)__cvta_generic_to_shared(&sK[1][0]);
    const uint svb0 = (uint)__cvta_generic_to_shared(&sV[0][0]);
    const uint svb1 = (uint)__cvta_generic_to_shared(&sV[1][0]);

    // ldmatrix lane->address offsets (in words)
    // K (trans): lane = d row; per nb: addr = d*KSW + nb*4
    const uint koff = (uint)lane * KSW;
    // V (non-trans): matrix m = lane/8; d = dbp*16 + (lane>>4)*8 + (lane&7),
    // word col = kc*8 + ((lane>>3)&1)*4
    const uint vrow = ((lane >> 4) * 8 + (lane & 7)) * VSW + ((lane >> 3) & 1) * 4;

    // ---- Q fragments, fp16 (scale includes log2 e) ----
    const float scale = 0.17677669529663687f * LOG2E;
    const int r0 = (q_row0 < NPIX) ? q_row0 : (NPIX - 1);
    const int r1 = (q_row1 < NPIX) ? q_row1 : (NPIX - 1);
    uint qa[2][4];
    #pragma unroll
    for (int kc = 0; kc < 2; kc++) {
        int d0 = kc * 16 + 2 * tig;
        const float* Qh = g_Q + (size_t)h * DHEAD * NPIX;
        qa[kc][0] = packh2(Qh[(d0)     * NPIX + r0] * scale, Qh[(d0 + 1) * NPIX + r0] * scale);
        qa[kc][1] = packh2(Qh[(d0)     * NPIX + r1] * scale, Qh[(d0 + 1) * NPIX + r1] * scale);
        qa[kc][2] = packh2(Qh[(d0 + 8) * NPIX + r0] * scale, Qh[(d0 + 9) * NPIX + r0] * scale);
        qa[kc][3] = packh2(Qh[(d0 + 8) * NPIX + r1] * scale, Qh[(d0 + 9) * NPIX + r1] * scale);
    }

    float o[4][4];
    #pragma unroll
    for (int db = 0; db < 4; db++)
        #pragma unroll
        for (int j = 0; j < 4; j++) o[db][j] = 0.f;

    float l0 = 0.f, l1 = 0.f;
    float4 rk, rv;

    const float* Kbase = g_K + (size_t)h * DHEAD * NPIX;
    const float* Vbase = g_V + (size_t)h * DHEAD * NPIX;

    // ---------- prologue: load + store first tile of this split ----------
    {
        int key0 = t0 * 64 + fkc * 4;   // always valid (t0*64 + 63 < NPIX)
        rk = *(const float4*)&Kbase[fd * NPIX + key0];
        rv = *(const float4*)&Vbase[fd * NPIX + key0];
        uint2 kk = make_uint2(packh2(rk.x, rk.y), packh2(rk.z, rk.w));
        uint2 vv = make_uint2(packh2(rv.x, rv.y), packh2(rv.z, rv.w));
        *(uint2*)&sK[0][fd * KSW + fkc * 2] = kk;
        *(uint2*)&sV[0][fd * VSW + fkc * 2] = vv;
    }
    __syncthreads();

    for (int t = t0; t < t_end; t++) {
        const int cur = (t - t0) & 1;
        const bool more = (t + 1 < t_end);
        const uint skc = cur ? skb1 : skb0;
        const uint svc = cur ? svb1 : svb0;

        // ---- issue next-tile global loads into registers ----
        if (more) {
            int key0 = (t + 1) * 64 + fkc * 4;
            bool ok = (key0 < NPIX);
            int keyc = ok ? key0 : 0;
            float4 ka = *(const float4*)&Kbase[fd * NPIX + keyc];
            float4 va = *(const float4*)&Vbase[fd * NPIX + keyc];
            rk = ok ? ka : make_float4(0.f, 0.f, 0.f, 0.f);
            rv = ok ? va : make_float4(0.f, 0.f, 0.f, 0.f);
        }

        // ---- S = Q K^T : per nb one ldmatrix.x4.trans gives all 4 B-regs ----
        float c[8][4];
        #pragma unroll
        for (int nb = 0; nb < 8; nb++) {
            c[nb][0] = c[nb][1] = c[nb][2] = c[nb][3] = 0.f;
            uint b00, b01, b10, b11;
            ldsm_x4_t(b00, b01, b10, b11, skc + (koff + nb * 4) * 4);
            mma_f16(c[nb], qa[0][0], qa[0][1], qa[0][2], qa[0][3], b00, b01);
            mma_f16(c[nb], qa[1][0], qa[1][1], qa[1][2], qa[1][3], b10, b11);
        }

        // ---- fused bias + exp2 + pack + PV (ldmatrix V) ----
        #pragma unroll
        for (int kc = 0; kc < 4; kc++) {
            const int nb0 = 2 * kc, nb1 = 2 * kc + 1;
            float2 lb0 = *(const float2*)&g_Lq[t * 64 + nb0 * 8 + 2 * tig];
            float2 lb1 = *(const float2*)&g_Lq[t * 64 + nb1 * 8 + 2 * tig];
            float p00 = ex2(c[nb0][0] + lb0.x);
            float p01 = ex2(c[nb0][1] + lb0.y);
            float p02 = ex2(c[nb0][2] + lb0.x);
            float p03 = ex2(c[nb0][3] + lb0.y);
            float p10 = ex2(c[nb1][0] + lb1.x);
            float p11 = ex2(c[nb1][1] + lb1.y);
            float p12 = ex2(c[nb1][2] + lb1.x);
            float p13 = ex2(c[nb1][3] + lb1.y);
            l0 += (p00 + p01) + (p10 + p11);
            l1 += (p02 + p03) + (p12 + p13);
            uint pa0 = packh2(p00, p01);
            uint pa1 = packh2(p02, p03);
            uint pa2 = packh2(p10, p11);
            uint pa3 = packh2(p12, p13);
            #pragma unroll
            for (int dbp = 0; dbp < 2; dbp++) {
                uint v00, v01, v10, v11;
                uint addr = svc + (vrow + dbp * 16 * VSW + kc * 8) * 4;
                ldsm_x4(v00, v01, v10, v11, addr);
                mma_f16(o[2 * dbp],     pa0, pa1, pa2, pa3, v00, v01);
                mma_f16(o[2 * dbp + 1], pa0, pa1, pa2, pa3, v10, v11);
            }
        }

        // ---- store next tile into the other buffer ----
        if (more) {
            const int nxt = cur ^ 1;
            uint2 kk = make_uint2(packh2(rk.x, rk.y), packh2(rk.z, rk.w));
            uint2 vv = make_uint2(packh2(rv.x, rv.y), packh2(rv.z, rv.w));
            *(uint2*)&sK[nxt][fd * KSW + fkc * 2] = kk;
            *(uint2*)&sV[nxt][fd * VSW + fkc * 2] = vv;
        }
        __syncthreads();
    }

    // ---- partial epilogue: quad-reduce l, write unnormalized partials ----
    l0 += __shfl_xor_sync(0xffffffffu, l0, 1);
    l0 += __shfl_xor_sync(0xffffffffu, l0, 2);
    l1 += __shfl_xor_sync(0xffffffffu, l1, 1);
    l1 += __shfl_xor_sync(0xffffffffu, l1, 2);
    if (tig == 0) {
        if (q_row0 < NPIX) g_Pl[z][h * NPIX + q_row0] = l0;
        if (q_row1 < NPIX) g_Pl[z][h * NPIX + q_row1] = l1;
    }
    #pragma unroll
    for (int db = 0; db < 4; db++) {
        int d = db * 8 + 2 * tig;
        if (q_row0 < NPIX)
            *(float2*)&g_Po[z][((size_t)h * NPIX + q_row0) * DHEAD + d] =
                make_float2(o[db][0], o[db][1]);
        if (q_row1 < NPIX)
            *(float2*)&g_Po[z][((size_t)h * NPIX + q_row1) * DHEAD + d] =
                make_float2(o[db][2], o[db][3]);
    }
}

// ============================================================================
// Combine split-K partials: O = (o0 + o1) / (l0 + l1), emit fp16-split pairs.
// ============================================================================
__global__ __launch_bounds__(256)
void attn_reduce()
{
    int idx = blockIdx.x * 256 + threadIdx.x;   // over NCP * NPIX
    if (idx >= NCP * NPIX) return;
    int cp = idx / NPIX;
    int n  = idx - cp * NPIX;
    int h  = cp >> 4;
    int dp = cp & 15;
    size_t ob = ((size_t)h * NPIX + n) * DHEAD + 2 * dp;
    float2 a0 = *(const float2*)&g_Po[0][ob];
    float2 a1 = *(const float2*)&g_Po[1][ob];
    float l = g_Pl[0][h * NPIX + n] + g_Pl[1][h * NPIX + n];
    float inv = 1.f / l;
    uint hi, lo;
    split_pair((a0.x + a1.x) * inv, (a0.y + a1.y) * inv, hi, lo);
    g_Oh2[idx] = hi;
    g_Ol2[idx] = lo;
}

// ============================================================================
extern "C" void kernel_launch(void* const* d_in, const int* in_sizes, int n_in,
                              void* d_out, int out_size)
{
    const float* query = (const float*)d_in[0];
    const float* q_w   = (const float*)d_in[1];
    const float* q_b   = (const float*)d_in[2];
    const float* k_w   = (const float*)d_in[3];
    const float* k_b   = (const float*)d_in[4];
    const float* v_w   = (const float*)d_in[5];
    const float* v_b   = (const float*)d_in[6];
    const float* p_w   = (const float*)d_in[7];
    const float* p_b   = (const float*)d_in[8];
    const float* lqw   = (const float*)d_in[9];
    float* out = (float*)d_out;

    split_wx<<<(NWP_TOT + NXP_TOT + 255) / 256, 256>>>(q_w, k_w, v_w, p_w, query);

    dim3 gq((NPIX + 63) / 64, 4, 3);                       // 65 x 4 x 3 = 780
    gemm_qkv<<<gq, 128>>>(q_b, k_b, v_b, lqw);

    dim3 ga((NPIX + 255) / 256, HEADS, NSPLIT);            // 17 x 8 x 2 = 272
    attn_kernel<<<ga, 512>>>();                            // -> g_Po/g_Pl

    attn_reduce<<<(NCP * NPIX + 255) / 256, 256>>>();      // -> g_Oh2/g_Ol2

    dim3 gp((NPIX + 63) / 64, 4, 1);                       // 65 x 4 = 260
    gemm_proj<<<gp, 128>>>(p_b, out);
}